// round 3
// baseline (speedup 1.0000x reference)
#include <cuda_runtime.h>

#define N_NODES 10000
#define N_PAD   10048
#define N_EDGES 160000
#define HID     512
#define EPS     1e-5f

// ---------------- scratch (static __device__, allowed) ----------------
__device__ float g_deg[N_NODES];
__device__ float g_dis[N_NODES];
__device__ float g_agg[N_PAD * HID];
__device__ float g_h  [N_PAD * HID];
__device__ float g_A  [N_PAD * 1024];
__device__ float g_B  [N_PAD * 1024];
__device__ float g_Z  [(size_t)N_EDGES * 1024];   // 640 MB
__device__ int   g_is64;

__device__ __forceinline__ float warp_sum(float v) {
#pragma unroll
    for (int o = 16; o > 0; o >>= 1) v += __shfl_xor_sync(0xffffffffu, v, o);
    return v;
}

// edge_index may be int32 (JAX default) or int64; g_is64 selects.
__device__ __forceinline__ int eidx(const void* __restrict__ ei, int pos) {
    return g_is64 ? (int)((const long long*)ei)[pos] : ((const int*)ei)[pos];
}

// ---------------- dtype detection ----------------
// If int64 little-endian with values < 2^31, every odd int32 word is 0.
__global__ void k_detect(const int* __restrict__ ei32) {
    if (threadIdx.x == 0) {
        int all0 = 1;
        for (int i = 0; i < 1000; i++)
            if (ei32[2 * i + 1] != 0) { all0 = 0; break; }
        g_is64 = all0;
    }
}

// ---------------- degree / normalization ----------------
__global__ void k_deg_zero() {
    int i = blockIdx.x * blockDim.x + threadIdx.x;
    if (i < N_NODES) g_deg[i] = 1.0f;              // self-loop contributes 1
}
__global__ void k_deg_acc(const void* __restrict__ ei) {
    int e = blockIdx.x * blockDim.x + threadIdx.x;
    if (e < N_EDGES) atomicAdd(&g_deg[eidx(ei, N_EDGES + e)], 1.0f);
}
__global__ void k_dis() {
    int i = blockIdx.x * blockDim.x + threadIdx.x;
    if (i < N_NODES) g_dis[i] = rsqrtf(g_deg[i]);  // deg >= 1 always
}

// ---------------- aggregation: agg = segsum(norm * h[row]) + selfloop ----------------
__global__ void k_agg_init(const float* __restrict__ h, float* __restrict__ agg,
                           int D, int cshift) {
    int idx = blockIdx.x * blockDim.x + threadIdx.x;
    if (idx >= (N_NODES << cshift)) return;
    int i = idx >> cshift, c = idx & ((1 << cshift) - 1);
    float s = g_dis[i]; s *= s;
    float4 v = *(const float4*)&h[i * D + c * 4];
    v.x *= s; v.y *= s; v.z *= s; v.w *= s;
    *(float4*)&agg[i * D + c * 4] = v;
}
__global__ void k_agg_edges(const float* __restrict__ h, float* __restrict__ agg,
                            const void* __restrict__ ei, int D, int cshift) {
    int idx = blockIdx.x * blockDim.x + threadIdx.x;
    if (idx >= (N_EDGES << cshift)) return;
    int e = idx >> cshift, c = idx & ((1 << cshift) - 1);
    int r  = eidx(ei, e);
    int cl = eidx(ei, N_EDGES + e);
    float nrm = g_dis[r] * g_dis[cl];
    float4 v = *(const float4*)&h[r * D + c * 4];
    float* dst = &agg[cl * D + c * 4];
    atomicAdd(dst + 0, nrm * v.x);
    atomicAdd(dst + 1, nrm * v.y);
    atomicAdd(dst + 2, nrm * v.z);
    atomicAdd(dst + 3, nrm * v.w);
}

// ---------------- GCN GEMM + bias + ReLU + LayerNorm ----------------
// A [10000 x K] (K=128 or 512), W [K x 512], out [10000 x 512]
// 16 rows/block, full 512-wide output so LN is done in-block.
__global__ void __launch_bounds__(256) k_gcn(
    const float* __restrict__ A, const float* __restrict__ W,
    const float* __restrict__ bias, const float* __restrict__ gam,
    const float* __restrict__ bet, float* __restrict__ out, int K)
{
    __shared__ float sA[16][16];
    __shared__ float sW[16][512];
    __shared__ float rsum[16][4], rsq[16][4];
    int t = threadIdx.x;
    int tx = t & 127, ty = t >> 7;       // thread owns cols tx*4..+3, rows ty+2j
    int row0 = blockIdx.x * 16;
    float acc[8][4];
#pragma unroll
    for (int j = 0; j < 8; j++) { acc[j][0]=0.f; acc[j][1]=0.f; acc[j][2]=0.f; acc[j][3]=0.f; }

    for (int k0 = 0; k0 < K; k0 += 16) {
        sA[t >> 4][t & 15] = A[(row0 + (t >> 4)) * K + k0 + (t & 15)];
#pragma unroll
        for (int i = 0; i < 8; i++) {
            int idx = t + i * 256;
            int kk = idx >> 7, c4 = idx & 127;
            *(float4*)&sW[kk][c4 * 4] = *(const float4*)&W[(k0 + kk) * 512 + c4 * 4];
        }
        __syncthreads();
#pragma unroll
        for (int kk = 0; kk < 16; kk++) {
            float4 w4 = *(float4*)&sW[kk][tx * 4];
#pragma unroll
            for (int j = 0; j < 8; j++) {
                float a = sA[ty + j * 2][kk];
                acc[j][0] += a * w4.x; acc[j][1] += a * w4.y;
                acc[j][2] += a * w4.z; acc[j][3] += a * w4.w;
            }
        }
        __syncthreads();
    }

    // bias + relu (relu BEFORE LN per reference)
    float4 b4 = *(const float4*)&bias[tx * 4];
    int lane = t & 31, quarter = (t >> 5) & 3;
#pragma unroll
    for (int j = 0; j < 8; j++) {
        acc[j][0] = fmaxf(acc[j][0] + b4.x, 0.f);
        acc[j][1] = fmaxf(acc[j][1] + b4.y, 0.f);
        acc[j][2] = fmaxf(acc[j][2] + b4.z, 0.f);
        acc[j][3] = fmaxf(acc[j][3] + b4.w, 0.f);
        int r = ty + j * 2;
        float s = acc[j][0] + acc[j][1] + acc[j][2] + acc[j][3];
        float q = acc[j][0]*acc[j][0] + acc[j][1]*acc[j][1]
                + acc[j][2]*acc[j][2] + acc[j][3]*acc[j][3];
        s = warp_sum(s); q = warp_sum(q);
        if (lane == 0) { rsum[r][quarter] = s; rsq[r][quarter] = q; }
    }
    __syncthreads();
    float4 g4  = *(const float4*)&gam[tx * 4];
    float4 be4 = *(const float4*)&bet[tx * 4];
#pragma unroll
    for (int j = 0; j < 8; j++) {
        int r = ty + j * 2;
        float s = rsum[r][0] + rsum[r][1] + rsum[r][2] + rsum[r][3];
        float q = rsq[r][0]  + rsq[r][1]  + rsq[r][2]  + rsq[r][3];
        float mu  = s * (1.f / 512.f);
        float var = q * (1.f / 512.f) - mu * mu;
        float rs  = rsqrtf(var + EPS);
        float4 o;
        o.x = (acc[j][0] - mu) * rs * g4.x + be4.x;
        o.y = (acc[j][1] - mu) * rs * g4.y + be4.y;
        o.z = (acc[j][2] - mu) * rs * g4.z + be4.z;
        o.w = (acc[j][3] - mu) * rs * g4.w + be4.w;
        *(float4*)&out[(row0 + r) * 512 + tx * 4] = o;
    }
}

// ---------------- plain tiled GEMM: C[N_PAD,1024] = Ain[N_PAD,512] @ W[512,1024] ----------------
__global__ void __launch_bounds__(256) k_gemm64(
    const float* __restrict__ Ain, const float* __restrict__ W, float* __restrict__ C)
{
    __shared__ float sA[64][20];   // pad 20: 16B-aligned rows, no bank conflicts
    __shared__ float sB[16][64];
    int t = threadIdx.x;
    int tx = t & 15, ty = t >> 4;
    int c0 = blockIdx.x * 64, r0 = blockIdx.y * 64;
    float acc[4][4];
#pragma unroll
    for (int i = 0; i < 4; i++) { acc[i][0]=0.f; acc[i][1]=0.f; acc[i][2]=0.f; acc[i][3]=0.f; }

    for (int k0 = 0; k0 < 512; k0 += 16) {
        {
            int r = t >> 2, q = t & 3;
            *(float4*)&sA[r][q * 4] = *(const float4*)&Ain[(r0 + r) * 512 + k0 + q * 4];
        }
        {
            int kk = t >> 4, c4 = t & 15;
            *(float4*)&sB[kk][c4 * 4] = *(const float4*)&W[(size_t)(k0 + kk) * 1024 + c0 + c4 * 4];
        }
        __syncthreads();
#pragma unroll
        for (int kk = 0; kk < 16; kk++) {
            float4 b4 = *(float4*)&sB[kk][tx * 4];
#pragma unroll
            for (int i = 0; i < 4; i++) {
                float a = sA[ty * 4 + i][kk];
                acc[i][0] += a * b4.x; acc[i][1] += a * b4.y;
                acc[i][2] += a * b4.z; acc[i][3] += a * b4.w;
            }
        }
        __syncthreads();
    }
#pragma unroll
    for (int i = 0; i < 4; i++) {
        float4 o; o.x = acc[i][0]; o.y = acc[i][1]; o.z = acc[i][2]; o.w = acc[i][3];
        *(float4*)&C[(size_t)(r0 + ty * 4 + i) * 1024 + c0 + tx * 4] = o;
    }
}

// ---------------- edge stage 1: Z[e] = relu(LN(A[s] + B[t] + mb0)) ----------------
__global__ void __launch_bounds__(256) k_edge1(
    const void* __restrict__ ei, const float* __restrict__ mb0,
    const float* __restrict__ g, const float* __restrict__ bt)
{
    int e = blockIdx.x;
    int t = threadIdx.x;
    int s = eidx(ei, e), d = eidx(ei, N_EDGES + e);
    float4 a = *(const float4*)&g_A[(size_t)s * 1024 + t * 4];
    float4 b = *(const float4*)&g_B[(size_t)d * 1024 + t * 4];
    float4 m = *(const float4*)&mb0[t * 4];
    float4 v;
    v.x = a.x + b.x + m.x; v.y = a.y + b.y + m.y;
    v.z = a.z + b.z + m.z; v.w = a.w + b.w + m.w;

    __shared__ float red[2][8];
    float sm = v.x + v.y + v.z + v.w;
    float sq = v.x*v.x + v.y*v.y + v.z*v.z + v.w*v.w;
    sm = warp_sum(sm); sq = warp_sum(sq);
    int warp = t >> 5, lane = t & 31;
    if (lane == 0) { red[0][warp] = sm; red[1][warp] = sq; }
    __syncthreads();
    float tot = 0.f, tot2 = 0.f;
#pragma unroll
    for (int w = 0; w < 8; w++) { tot += red[0][w]; tot2 += red[1][w]; }
    float mu  = tot * (1.f / 1024.f);
    float var = tot2 * (1.f / 1024.f) - mu * mu;
    float rs  = rsqrtf(var + EPS);
    float4 gg = *(const float4*)&g[t * 4];
    float4 bb = *(const float4*)&bt[t * 4];
    v.x = fmaxf((v.x - mu) * rs * gg.x + bb.x, 0.f);
    v.y = fmaxf((v.y - mu) * rs * gg.y + bb.y, 0.f);
    v.z = fmaxf((v.z - mu) * rs * gg.z + bb.z, 0.f);
    v.w = fmaxf((v.w - mu) * rs * gg.w + bb.w, 0.f);
    *(float4*)&g_Z[(size_t)e * 1024 + t * 4] = v;
}

// ---------------- edge stage 2: out = relu(LN(Z @ mw1 + mb1)) . mw2 + mb2 ----------------
// 32 edges/block, full 512-wide output (LN in-block), fused final dot product.
__global__ void __launch_bounds__(256) k_edge2(
    const float* __restrict__ W1, const float* __restrict__ mb1,
    const float* __restrict__ g, const float* __restrict__ bt,
    const float* __restrict__ mw2, const float* __restrict__ mb2,
    float* __restrict__ out)
{
    __shared__ float sZ[32][17];
    __shared__ float sW[16][512];
    __shared__ float rsum[32][2], rsq[32][2], rdot[32][2];
    int t = threadIdx.x;
    int tx = t & 63, ty = t >> 6;        // cols tx*4..+3 and 256+tx*4..+3 ; rows ty+4j
    int e0 = blockIdx.x * 32;
    float acc[8][8];
#pragma unroll
    for (int j = 0; j < 8; j++)
#pragma unroll
        for (int c = 0; c < 8; c++) acc[j][c] = 0.f;

    for (int k0 = 0; k0 < 1024; k0 += 16) {
#pragma unroll
        for (int i = 0; i < 2; i++) {
            int idx = t + i * 256;
            sZ[idx >> 4][idx & 15] = g_Z[(size_t)(e0 + (idx >> 4)) * 1024 + k0 + (idx & 15)];
        }
#pragma unroll
        for (int i = 0; i < 8; i++) {
            int idx = t + i * 256;
            int kk = idx >> 7, c4 = idx & 127;
            *(float4*)&sW[kk][c4 * 4] = *(const float4*)&W1[(k0 + kk) * 512 + c4 * 4];
        }
        __syncthreads();
#pragma unroll
        for (int kk = 0; kk < 16; kk++) {
            float4 wA = *(float4*)&sW[kk][tx * 4];
            float4 wB = *(float4*)&sW[kk][256 + tx * 4];
#pragma unroll
            for (int j = 0; j < 8; j++) {
                float a = sZ[ty + 4 * j][kk];
                acc[j][0] += a * wA.x; acc[j][1] += a * wA.y;
                acc[j][2] += a * wA.z; acc[j][3] += a * wA.w;
                acc[j][4] += a * wB.x; acc[j][5] += a * wB.y;
                acc[j][6] += a * wB.z; acc[j][7] += a * wB.w;
            }
        }
        __syncthreads();
    }

    int lane = t & 31, half = (t >> 5) & 1;
    float4 bA = *(const float4*)&mb1[tx * 4];
    float4 bB = *(const float4*)&mb1[256 + tx * 4];
#pragma unroll
    for (int j = 0; j < 8; j++) {
        acc[j][0] += bA.x; acc[j][1] += bA.y; acc[j][2] += bA.z; acc[j][3] += bA.w;
        acc[j][4] += bB.x; acc[j][5] += bB.y; acc[j][6] += bB.z; acc[j][7] += bB.w;
        int r = ty + 4 * j;
        float s = 0.f, q = 0.f;
#pragma unroll
        for (int c = 0; c < 8; c++) { s += acc[j][c]; q += acc[j][c] * acc[j][c]; }
        s = warp_sum(s); q = warp_sum(q);
        if (lane == 0) { rsum[r][half] = s; rsq[r][half] = q; }
    }
    __syncthreads();
    float4 gA  = *(const float4*)&g[tx * 4];
    float4 gB  = *(const float4*)&g[256 + tx * 4];
    float4 btA = *(const float4*)&bt[tx * 4];
    float4 btB = *(const float4*)&bt[256 + tx * 4];
    float4 wA2 = *(const float4*)&mw2[tx * 4];
    float4 wB2 = *(const float4*)&mw2[256 + tx * 4];
#pragma unroll
    for (int j = 0; j < 8; j++) {
        int r = ty + 4 * j;
        float s = rsum[r][0] + rsum[r][1];
        float q = rsq[r][0]  + rsq[r][1];
        float mu  = s * (1.f / 512.f);
        float var = q * (1.f / 512.f) - mu * mu;
        float rs  = rsqrtf(var + EPS);
        float dot =
            fmaxf((acc[j][0] - mu) * rs * gA.x + btA.x, 0.f) * wA2.x +
            fmaxf((acc[j][1] - mu) * rs * gA.y + btA.y, 0.f) * wA2.y +
            fmaxf((acc[j][2] - mu) * rs * gA.z + btA.z, 0.f) * wA2.z +
            fmaxf((acc[j][3] - mu) * rs * gA.w + btA.w, 0.f) * wA2.w +
            fmaxf((acc[j][4] - mu) * rs * gB.x + btB.x, 0.f) * wB2.x +
            fmaxf((acc[j][5] - mu) * rs * gB.y + btB.y, 0.f) * wB2.y +
            fmaxf((acc[j][6] - mu) * rs * gB.z + btB.z, 0.f) * wB2.z +
            fmaxf((acc[j][7] - mu) * rs * gB.w + btB.w, 0.f) * wB2.w;
        dot = warp_sum(dot);
        if (lane == 0) rdot[r][half] = dot;
    }
    __syncthreads();
    if (tx == 0) {
#pragma unroll
        for (int j = 0; j < 8; j++) {
            int r = ty + 4 * j;
            out[e0 + r] = rdot[r][0] + rdot[r][1] + mb2[0];
        }
    }
}

// ---------------- launch ----------------
extern "C" void kernel_launch(void* const* d_in, const int* in_sizes, int n_in,
                              void* d_out, int out_size)
{
    const float* x    = (const float*)d_in[0];
    const void*  ei   = d_in[1];                  // int32 or int64, detected on device
    const float* w0   = (const float*)d_in[2];
    const float* b0   = (const float*)d_in[3];
    const float* ws   = (const float*)d_in[4];
    const float* bs   = (const float*)d_in[5];
    const float* lng  = (const float*)d_in[6];
    const float* lnb  = (const float*)d_in[7];
    const float* mw0  = (const float*)d_in[8];
    const float* mb0  = (const float*)d_in[9];
    const float* mg0  = (const float*)d_in[10];
    const float* mbt0 = (const float*)d_in[11];
    const float* mw1  = (const float*)d_in[12];
    const float* mb1  = (const float*)d_in[13];
    const float* mg1  = (const float*)d_in[14];
    const float* mbt1 = (const float*)d_in[15];
    const float* mw2  = (const float*)d_in[16];
    const float* mb2  = (const float*)d_in[17];
    float* out = (float*)d_out;

    float *p_agg, *p_h, *p_A, *p_B;
    cudaGetSymbolAddress((void**)&p_agg, g_agg);
    cudaGetSymbolAddress((void**)&p_h,   g_h);
    cudaGetSymbolAddress((void**)&p_A,   g_A);
    cudaGetSymbolAddress((void**)&p_B,   g_B);

    // dtype detection + normalization
    k_detect<<<1, 32>>>((const int*)ei);
    k_deg_zero<<<(N_NODES + 255) / 256, 256>>>();
    k_deg_acc <<<(N_EDGES + 255) / 256, 256>>>(ei);
    k_dis     <<<(N_NODES + 255) / 256, 256>>>();

    // layer 0 (aggregate in 128-dim input space, then GEMM 128->512)
    k_agg_init <<<(N_NODES * 32 + 255) / 256, 256>>>(x, p_agg, 128, 5);
    k_agg_edges<<<(N_EDGES * 32 + 255) / 256, 256>>>(x, p_agg, ei, 128, 5);
    k_gcn<<<N_NODES / 16, 256>>>(p_agg, w0, b0, lng, lnb, p_h, 128);

    // layers 1..3
    for (int i = 1; i < 4; i++) {
        k_agg_init <<<(N_NODES * 128 + 255) / 256, 256>>>(p_h, p_agg, 512, 7);
        k_agg_edges<<<(N_EDGES * 128 + 255) / 256, 256>>>(p_h, p_agg, ei, 512, 7);
        k_gcn<<<N_NODES / 16, 256>>>(p_agg, ws + (size_t)(i - 1) * 512 * 512,
                                     bs + (i - 1) * 512, lng + i * 512, lnb + i * 512,
                                     p_h, 512);
    }

    // edge MLP first layer factored per-node: A = h @ mw0[:512], B = h @ mw0[512:]
    dim3 gAB(16, N_PAD / 64);
    k_gemm64<<<gAB, 256>>>(p_h, mw0, p_A);
    k_gemm64<<<gAB, 256>>>(p_h, mw0 + (size_t)512 * 1024, p_B);

    // per-edge: z = relu(LN(A[s]+B[t]+mb0))
    k_edge1<<<N_EDGES, 256>>>(ei, mb0, mg0, mbt0);

    // z @ mw1 + LN + relu + dot(mw2) + mb2  (fused)
    k_edge2<<<N_EDGES / 32, 256>>>(mw1, mb1, mg1, mbt1, mw2, mb2, out);
}

// round 6
// speedup vs baseline: 1.0035x; 1.0035x over previous
#include <cuda_runtime.h>

#define N_NODES 10000
#define N_PAD   10048
#define N_EDGES 160000
#define HID     512
#define EPS     1e-5f

// ---------------- scratch (static __device__, allowed) ----------------
__device__ float g_deg[N_NODES];
__device__ float g_dis[N_NODES];
__device__ float g_agg[N_PAD * HID];
__device__ float g_h  [N_PAD * HID];
__device__ float g_A  [N_PAD * 1024];
__device__ float g_B  [N_PAD * 1024];
__device__ float g_Z  [(size_t)N_EDGES * 1024];   // 640 MB
__device__ int   g_is64;

__device__ __forceinline__ float warp_sum(float v) {
#pragma unroll
    for (int o = 16; o > 0; o >>= 1) v += __shfl_xor_sync(0xffffffffu, v, o);
    return v;
}

// ---- packed fp32x2 FMA (sm_103a; ptxas never emits FFMA2 from C++) ----
#define FMA2(d, a, b) asm("fma.rn.f32x2 %0, %1, %2, %0;" : "+l"(d) : "l"(a), "l"(b))
__device__ __forceinline__ unsigned long long bcast2(float a) {
    unsigned long long r;
    asm("mov.b64 %0, {%1, %1};" : "=l"(r) : "f"(a));
    return r;
}
__device__ __forceinline__ void unpack2(unsigned long long d, float& lo, float& hi) {
    asm("mov.b64 {%0, %1}, %2;" : "=f"(lo), "=f"(hi) : "l"(d));
}

// edge_index may be int32 (JAX default) or int64; g_is64 selects.
__device__ __forceinline__ int eidx(const void* __restrict__ ei, int pos) {
    return g_is64 ? (int)((const long long*)ei)[pos] : ((const int*)ei)[pos];
}

// ---------------- dtype detection ----------------
__global__ void k_detect(const int* __restrict__ ei32) {
    if (threadIdx.x == 0) {
        int all0 = 1;
        for (int i = 0; i < 1000; i++)
            if (ei32[2 * i + 1] != 0) { all0 = 0; break; }
        g_is64 = all0;
    }
}

// ---------------- degree / normalization ----------------
__global__ void k_deg_zero() {
    int i = blockIdx.x * blockDim.x + threadIdx.x;
    if (i < N_NODES) g_deg[i] = 1.0f;              // self-loop contributes 1
}
__global__ void k_deg_acc(const void* __restrict__ ei) {
    int e = blockIdx.x * blockDim.x + threadIdx.x;
    if (e < N_EDGES) atomicAdd(&g_deg[eidx(ei, N_EDGES + e)], 1.0f);
}
__global__ void k_dis() {
    int i = blockIdx.x * blockDim.x + threadIdx.x;
    if (i < N_NODES) g_dis[i] = rsqrtf(g_deg[i]);  // deg >= 1 always
}

// ---------------- aggregation: agg = segsum(norm * h[row]) + selfloop ----------------
__global__ void k_agg_init(const float* __restrict__ h, float* __restrict__ agg,
                           int D, int cshift) {
    int idx = blockIdx.x * blockDim.x + threadIdx.x;
    if (idx >= (N_NODES << cshift)) return;
    int i = idx >> cshift, c = idx & ((1 << cshift) - 1);
    float s = g_dis[i]; s *= s;
    float4 v = *(const float4*)&h[i * D + c * 4];
    v.x *= s; v.y *= s; v.z *= s; v.w *= s;
    *(float4*)&agg[i * D + c * 4] = v;
}
__global__ void k_agg_edges(const float* __restrict__ h, float* __restrict__ agg,
                            const void* __restrict__ ei, int D, int cshift) {
    int idx = blockIdx.x * blockDim.x + threadIdx.x;
    if (idx >= (N_EDGES << cshift)) return;
    int e = idx >> cshift, c = idx & ((1 << cshift) - 1);
    int r  = eidx(ei, e);
    int cl = eidx(ei, N_EDGES + e);
    float nrm = g_dis[r] * g_dis[cl];
    float4 v = *(const float4*)&h[r * D + c * 4];
    float* dst = &agg[cl * D + c * 4];
    atomicAdd(dst + 0, nrm * v.x);
    atomicAdd(dst + 1, nrm * v.y);
    atomicAdd(dst + 2, nrm * v.z);
    atomicAdd(dst + 3, nrm * v.w);
}

// ---------------- GCN GEMM + bias + ReLU + LayerNorm ----------------
__global__ void __launch_bounds__(256) k_gcn(
    const float* __restrict__ A, const float* __restrict__ W,
    const float* __restrict__ bias, const float* __restrict__ gam,
    const float* __restrict__ bet, float* __restrict__ out, int K)
{
    __shared__ float sA[16][16];
    __shared__ float sW[16][512];
    __shared__ float rsum[16][4], rsq[16][4];
    int t = threadIdx.x;
    int tx = t & 127, ty = t >> 7;       // thread owns cols tx*4..+3, rows ty+2j
    int row0 = blockIdx.x * 16;
    unsigned long long a64[8][2];
#pragma unroll
    for (int j = 0; j < 8; j++) { a64[j][0] = 0ull; a64[j][1] = 0ull; }

    for (int k0 = 0; k0 < K; k0 += 16) {
        sA[t >> 4][t & 15] = A[(row0 + (t >> 4)) * K + k0 + (t & 15)];
#pragma unroll
        for (int i = 0; i < 8; i++) {
            int idx = t + i * 256;
            int kk = idx >> 7, c4 = idx & 127;
            *(float4*)&sW[kk][c4 * 4] = *(const float4*)&W[(k0 + kk) * 512 + c4 * 4];
        }
        __syncthreads();
#pragma unroll
        for (int kk = 0; kk < 16; kk++) {
            ulonglong2 w2 = *(ulonglong2*)&sW[kk][tx * 4];
#pragma unroll
            for (int j = 0; j < 8; j++) {
                unsigned long long aa = bcast2(sA[ty + j * 2][kk]);
                FMA2(a64[j][0], aa, w2.x);
                FMA2(a64[j][1], aa, w2.y);
            }
        }
        __syncthreads();
    }

    float acc[8][4];
#pragma unroll
    for (int j = 0; j < 8; j++) {
        unpack2(a64[j][0], acc[j][0], acc[j][1]);
        unpack2(a64[j][1], acc[j][2], acc[j][3]);
    }

    // bias + relu (relu BEFORE LN per reference)
    float4 b4 = *(const float4*)&bias[tx * 4];
    int lane = t & 31, quarter = (t >> 5) & 3;
#pragma unroll
    for (int j = 0; j < 8; j++) {
        acc[j][0] = fmaxf(acc[j][0] + b4.x, 0.f);
        acc[j][1] = fmaxf(acc[j][1] + b4.y, 0.f);
        acc[j][2] = fmaxf(acc[j][2] + b4.z, 0.f);
        acc[j][3] = fmaxf(acc[j][3] + b4.w, 0.f);
        int r = ty + j * 2;
        float s = acc[j][0] + acc[j][1] + acc[j][2] + acc[j][3];
        float q = acc[j][0]*acc[j][0] + acc[j][1]*acc[j][1]
                + acc[j][2]*acc[j][2] + acc[j][3]*acc[j][3];
        s = warp_sum(s); q = warp_sum(q);
        if (lane == 0) { rsum[r][quarter] = s; rsq[r][quarter] = q; }
    }
    __syncthreads();
    float4 g4  = *(const float4*)&gam[tx * 4];
    float4 be4 = *(const float4*)&bet[tx * 4];
#pragma unroll
    for (int j = 0; j < 8; j++) {
        int r = ty + j * 2;
        float s = rsum[r][0] + rsum[r][1] + rsum[r][2] + rsum[r][3];
        float q = rsq[r][0]  + rsq[r][1]  + rsq[r][2]  + rsq[r][3];
        float mu  = s * (1.f / 512.f);
        float var = q * (1.f / 512.f) - mu * mu;
        float rs  = rsqrtf(var + EPS);
        float4 o;
        o.x = (acc[j][0] - mu) * rs * g4.x + be4.x;
        o.y = (acc[j][1] - mu) * rs * g4.y + be4.y;
        o.z = (acc[j][2] - mu) * rs * g4.z + be4.z;
        o.w = (acc[j][3] - mu) * rs * g4.w + be4.w;
        *(float4*)&out[(row0 + r) * 512 + tx * 4] = o;
    }
}

// ---------------- plain tiled GEMM: C[N_PAD,1024] = Ain[N_PAD,512] @ W[512,1024] ----------------
__global__ void __launch_bounds__(256) k_gemm64(
    const float* __restrict__ Ain, const float* __restrict__ W, float* __restrict__ C)
{
    __shared__ float sA[64][20];   // pad 20: 16B-aligned rows, no bank conflicts
    __shared__ float sB[16][64];
    int t = threadIdx.x;
    int tx = t & 15, ty = t >> 4;
    int c0 = blockIdx.x * 64, r0 = blockIdx.y * 64;
    unsigned long long a64[4][2];
#pragma unroll
    for (int i = 0; i < 4; i++) { a64[i][0] = 0ull; a64[i][1] = 0ull; }

    for (int k0 = 0; k0 < 512; k0 += 16) {
        {
            int r = t >> 2, q = t & 3;
            *(float4*)&sA[r][q * 4] = *(const float4*)&Ain[(r0 + r) * 512 + k0 + q * 4];
        }
        {
            int kk = t >> 4, c4 = t & 15;
            *(float4*)&sB[kk][c4 * 4] = *(const float4*)&W[(size_t)(k0 + kk) * 1024 + c0 + c4 * 4];
        }
        __syncthreads();
#pragma unroll
        for (int kk = 0; kk < 16; kk++) {
            ulonglong2 b2 = *(ulonglong2*)&sB[kk][tx * 4];
#pragma unroll
            for (int i = 0; i < 4; i++) {
                unsigned long long aa = bcast2(sA[ty * 4 + i][kk]);
                FMA2(a64[i][0], aa, b2.x);
                FMA2(a64[i][1], aa, b2.y);
            }
        }
        __syncthreads();
    }
#pragma unroll
    for (int i = 0; i < 4; i++) {
        float4 o;
        unpack2(a64[i][0], o.x, o.y);
        unpack2(a64[i][1], o.z, o.w);
        *(float4*)&C[(size_t)(r0 + ty * 4 + i) * 1024 + c0 + tx * 4] = o;
    }
}

// ---------------- edge stage 1: Z[e] = relu(LN(A[s] + B[t] + mb0)) ----------------
__global__ void __launch_bounds__(256) k_edge1(
    const void* __restrict__ ei, const float* __restrict__ mb0,
    const float* __restrict__ g, const float* __restrict__ bt)
{
    int e = blockIdx.x;
    int t = threadIdx.x;
    int s = eidx(ei, e), d = eidx(ei, N_EDGES + e);
    float4 a = *(const float4*)&g_A[(size_t)s * 1024 + t * 4];
    float4 b = *(const float4*)&g_B[(size_t)d * 1024 + t * 4];
    float4 m = *(const float4*)&mb0[t * 4];
    float4 v;
    v.x = a.x + b.x + m.x; v.y = a.y + b.y + m.y;
    v.z = a.z + b.z + m.z; v.w = a.w + b.w + m.w;

    __shared__ float red[2][8];
    float sm = v.x + v.y + v.z + v.w;
    float sq = v.x*v.x + v.y*v.y + v.z*v.z + v.w*v.w;
    sm = warp_sum(sm); sq = warp_sum(sq);
    int warp = t >> 5, lane = t & 31;
    if (lane == 0) { red[0][warp] = sm; red[1][warp] = sq; }
    __syncthreads();
    float tot = 0.f, tot2 = 0.f;
#pragma unroll
    for (int w = 0; w < 8; w++) { tot += red[0][w]; tot2 += red[1][w]; }
    float mu  = tot * (1.f / 1024.f);
    float var = tot2 * (1.f / 1024.f) - mu * mu;
    float rs  = rsqrtf(var + EPS);
    float4 gg = *(const float4*)&g[t * 4];
    float4 bb = *(const float4*)&bt[t * 4];
    v.x = fmaxf((v.x - mu) * rs * gg.x + bb.x, 0.f);
    v.y = fmaxf((v.y - mu) * rs * gg.y + bb.y, 0.f);
    v.z = fmaxf((v.z - mu) * rs * gg.z + bb.z, 0.f);
    v.w = fmaxf((v.w - mu) * rs * gg.w + bb.w, 0.f);
    *(float4*)&g_Z[(size_t)e * 1024 + t * 4] = v;
}

// ---------------- edge stage 2: out = relu(LN(Z @ mw1 + mb1)) . mw2 + mb2 ----------------
// 32 edges/block, full 512-wide output (LN in-block), fused final dot product.
__global__ void __launch_bounds__(256) k_edge2(
    const float* __restrict__ W1, const float* __restrict__ mb1,
    const float* __restrict__ g, const float* __restrict__ bt,
    const float* __restrict__ mw2, const float* __restrict__ mb2,
    float* __restrict__ out)
{
    __shared__ float sZ[32][17];
    __shared__ float sW[16][512];
    __shared__ float rsum[32][2], rsq[32][2], rdot[32][2];
    int t = threadIdx.x;
    int tx = t & 63, ty = t >> 6;        // cols tx*4..+3 and 256+tx*4..+3 ; rows ty+4j
    int e0 = blockIdx.x * 32;
    unsigned long long a64[8][4];
#pragma unroll
    for (int j = 0; j < 8; j++)
#pragma unroll
        for (int p = 0; p < 4; p++) a64[j][p] = 0ull;

    for (int k0 = 0; k0 < 1024; k0 += 16) {
#pragma unroll
        for (int i = 0; i < 2; i++) {
            int idx = t + i * 256;
            sZ[idx >> 4][idx & 15] = g_Z[(size_t)(e0 + (idx >> 4)) * 1024 + k0 + (idx & 15)];
        }
#pragma unroll
        for (int i = 0; i < 8; i++) {
            int idx = t + i * 256;
            int kk = idx >> 7, c4 = idx & 127;
            *(float4*)&sW[kk][c4 * 4] = *(const float4*)&W1[(k0 + kk) * 512 + c4 * 4];
        }
        __syncthreads();
#pragma unroll
        for (int kk = 0; kk < 16; kk++) {
            ulonglong2 wA = *(ulonglong2*)&sW[kk][tx * 4];
            ulonglong2 wB = *(ulonglong2*)&sW[kk][256 + tx * 4];
#pragma unroll
            for (int j = 0; j < 8; j++) {
                unsigned long long aa = bcast2(sZ[ty + 4 * j][kk]);
                FMA2(a64[j][0], aa, wA.x);
                FMA2(a64[j][1], aa, wA.y);
                FMA2(a64[j][2], aa, wB.x);
                FMA2(a64[j][3], aa, wB.y);
            }
        }
        __syncthreads();
    }

    float acc[8][8];
#pragma unroll
    for (int j = 0; j < 8; j++) {
        unpack2(a64[j][0], acc[j][0], acc[j][1]);
        unpack2(a64[j][1], acc[j][2], acc[j][3]);
        unpack2(a64[j][2], acc[j][4], acc[j][5]);
        unpack2(a64[j][3], acc[j][6], acc[j][7]);
    }

    int lane = t & 31, half = (t >> 5) & 1;
    float4 bA = *(const float4*)&mb1[tx * 4];
    float4 bB = *(const float4*)&mb1[256 + tx * 4];
#pragma unroll
    for (int j = 0; j < 8; j++) {
        acc[j][0] += bA.x; acc[j][1] += bA.y; acc[j][2] += bA.z; acc[j][3] += bA.w;
        acc[j][4] += bB.x; acc[j][5] += bB.y; acc[j][6] += bB.z; acc[j][7] += bB.w;
        int r = ty + 4 * j;
        float s = 0.f, q = 0.f;
#pragma unroll
        for (int c = 0; c < 8; c++) { s += acc[j][c]; q += acc[j][c] * acc[j][c]; }
        s = warp_sum(s); q = warp_sum(q);
        if (lane == 0) { rsum[r][half] = s; rsq[r][half] = q; }
    }
    __syncthreads();
    float4 gA  = *(const float4*)&g[tx * 4];
    float4 gB  = *(const float4*)&g[256 + tx * 4];
    float4 btA = *(const float4*)&bt[tx * 4];
    float4 btB = *(const float4*)&bt[256 + tx * 4];
    float4 wA2 = *(const float4*)&mw2[tx * 4];
    float4 wB2 = *(const float4*)&mw2[256 + tx * 4];
#pragma unroll
    for (int j = 0; j < 8; j++) {
        int r = ty + 4 * j;
        float s = rsum[r][0] + rsum[r][1];
        float q = rsq[r][0]  + rsq[r][1];
        float mu  = s * (1.f / 512.f);
        float var = q * (1.f / 512.f) - mu * mu;
        float rs  = rsqrtf(var + EPS);
        float dot =
            fmaxf((acc[j][0] - mu) * rs * gA.x + btA.x, 0.f) * wA2.x +
            fmaxf((acc[j][1] - mu) * rs * gA.y + btA.y, 0.f) * wA2.y +
            fmaxf((acc[j][2] - mu) * rs * gA.z + btA.z, 0.f) * wA2.z +
            fmaxf((acc[j][3] - mu) * rs * gA.w + btA.w, 0.f) * wA2.w +
            fmaxf((acc[j][4] - mu) * rs * gB.x + btB.x, 0.f) * wB2.x +
            fmaxf((acc[j][5] - mu) * rs * gB.y + btB.y, 0.f) * wB2.y +
            fmaxf((acc[j][6] - mu) * rs * gB.z + btB.z, 0.f) * wB2.z +
            fmaxf((acc[j][7] - mu) * rs * gB.w + btB.w, 0.f) * wB2.w;
        dot = warp_sum(dot);
        if (lane == 0) rdot[r][half] = dot;
    }
    __syncthreads();
    if (tx == 0) {
#pragma unroll
        for (int j = 0; j < 8; j++) {
            int r = ty + 4 * j;
            out[e0 + r] = rdot[r][0] + rdot[r][1] + mb2[0];
        }
    }
}

// ---------------- launch ----------------
extern "C" void kernel_launch(void* const* d_in, const int* in_sizes, int n_in,
                              void* d_out, int out_size)
{
    const float* x    = (const float*)d_in[0];
    const void*  ei   = d_in[1];                  // int32 or int64, detected on device
    const float* w0   = (const float*)d_in[2];
    const float* b0   = (const float*)d_in[3];
    const float* ws   = (const float*)d_in[4];
    const float* bs   = (const float*)d_in[5];
    const float* lng  = (const float*)d_in[6];
    const float* lnb  = (const float*)d_in[7];
    const float* mw0  = (const float*)d_in[8];
    const float* mb0  = (const float*)d_in[9];
    const float* mg0  = (const float*)d_in[10];
    const float* mbt0 = (const float*)d_in[11];
    const float* mw1  = (const float*)d_in[12];
    const float* mb1  = (const float*)d_in[13];
    const float* mg1  = (const float*)d_in[14];
    const float* mbt1 = (const float*)d_in[15];
    const float* mw2  = (const float*)d_in[16];
    const float* mb2  = (const float*)d_in[17];
    float* out = (float*)d_out;

    float *p_agg, *p_h, *p_A, *p_B;
    cudaGetSymbolAddress((void**)&p_agg, g_agg);
    cudaGetSymbolAddress((void**)&p_h,   g_h);
    cudaGetSymbolAddress((void**)&p_A,   g_A);
    cudaGetSymbolAddress((void**)&p_B,   g_B);

    // dtype detection + normalization
    k_detect<<<1, 32>>>((const int*)ei);
    k_deg_zero<<<(N_NODES + 255) / 256, 256>>>();
    k_deg_acc <<<(N_EDGES + 255) / 256, 256>>>(ei);
    k_dis     <<<(N_NODES + 255) / 256, 256>>>();

    // layer 0 (aggregate in 128-dim input space, then GEMM 128->512)
    k_agg_init <<<(N_NODES * 32 + 255) / 256, 256>>>(x, p_agg, 128, 5);
    k_agg_edges<<<(N_EDGES * 32 + 255) / 256, 256>>>(x, p_agg, ei, 128, 5);
    k_gcn<<<N_NODES / 16, 256>>>(p_agg, w0, b0, lng, lnb, p_h, 128);

    // layers 1..3
    for (int i = 1; i < 4; i++) {
        k_agg_init <<<(N_NODES * 128 + 255) / 256, 256>>>(p_h, p_agg, 512, 7);
        k_agg_edges<<<(N_EDGES * 128 + 255) / 256, 256>>>(p_h, p_agg, ei, 512, 7);
        k_gcn<<<N_NODES / 16, 256>>>(p_agg, ws + (size_t)(i - 1) * 512 * 512,
                                     bs + (i - 1) * 512, lng + i * 512, lnb + i * 512,
                                     p_h, 512);
    }

    // edge MLP first layer factored per-node: A = h @ mw0[:512], B = h @ mw0[512:]
    dim3 gAB(16, N_PAD / 64);
    k_gemm64<<<gAB, 256>>>(p_h, mw0, p_A);
    k_gemm64<<<gAB, 256>>>(p_h, mw0 + (size_t)512 * 1024, p_B);

    // per-edge: z = relu(LN(A[s]+B[t]+mb0))
    k_edge1<<<N_EDGES, 256>>>(ei, mb0, mg0, mbt0);

    // z @ mw1 + LN + relu + dot(mw2) + mb2  (fused)
    k_edge2<<<N_EDGES / 32, 256>>>(mw1, mb1, mg1, mbt1, mw2, mb2, out);
}

// round 7
// speedup vs baseline: 1.0468x; 1.0432x over previous
#include <cuda_runtime.h>

#define N_NODES 10000
#define N_PAD   10048
#define N_EDGES 160000
#define HID     512
#define EPS     1e-5f

// ---------------- scratch (static __device__, allowed) ----------------
__device__ float g_deg[N_NODES];
__device__ float g_dis[N_NODES];
__device__ float g_agg[N_PAD * HID];
__device__ float g_h  [N_PAD * HID];
__device__ float g_A  [N_PAD * 1024];
__device__ float g_B  [N_PAD * 1024];
__device__ float g_Z  [(size_t)N_EDGES * 1024];   // 640 MB
__device__ int   g_is64;

__device__ __forceinline__ float warp_sum(float v) {
#pragma unroll
    for (int o = 16; o > 0; o >>= 1) v += __shfl_xor_sync(0xffffffffu, v, o);
    return v;
}

// ---- packed fp32x2 FMA ----
#define FMA2(d, a, b) asm("fma.rn.f32x2 %0, %1, %2, %0;" : "+l"(d) : "l"(a), "l"(b))
__device__ __forceinline__ unsigned long long bcast2(float a) {
    unsigned long long r;
    asm("mov.b64 %0, {%1, %1};" : "=l"(r) : "f"(a));
    return r;
}
__device__ __forceinline__ void unpack2(unsigned long long d, float& lo, float& hi) {
    asm("mov.b64 {%0, %1}, %2;" : "=f"(lo), "=f"(hi) : "l"(d));
}

// ---- tf32 helpers ----
__device__ __forceinline__ unsigned tf32cvt(float f) {
    unsigned u; asm("cvt.rna.tf32.f32 %0, %1;" : "=r"(u) : "f"(f)); return u;
}
__device__ __forceinline__ void mma_tf32(float* c,
    unsigned a0, unsigned a1, unsigned a2, unsigned a3,
    unsigned b0, unsigned b1)
{
    asm volatile(
        "mma.sync.aligned.m16n8k8.row.col.f32.tf32.tf32.f32 "
        "{%0,%1,%2,%3}, {%4,%5,%6,%7}, {%8,%9}, {%0,%1,%2,%3};"
        : "+f"(c[0]), "+f"(c[1]), "+f"(c[2]), "+f"(c[3])
        : "r"(a0), "r"(a1), "r"(a2), "r"(a3), "r"(b0), "r"(b1));
}

// edge_index may be int32 (JAX default) or int64; g_is64 selects.
__device__ __forceinline__ int eidx(const void* __restrict__ ei, int pos) {
    return g_is64 ? (int)((const long long*)ei)[pos] : ((const int*)ei)[pos];
}

// ---------------- dtype detection ----------------
__global__ void k_detect(const int* __restrict__ ei32) {
    if (threadIdx.x == 0) {
        int all0 = 1;
        for (int i = 0; i < 1000; i++)
            if (ei32[2 * i + 1] != 0) { all0 = 0; break; }
        g_is64 = all0;
    }
}

// ---------------- degree / normalization ----------------
__global__ void k_deg_zero() {
    int i = blockIdx.x * blockDim.x + threadIdx.x;
    if (i < N_NODES) g_deg[i] = 1.0f;              // self-loop contributes 1
}
__global__ void k_deg_acc(const void* __restrict__ ei) {
    int e = blockIdx.x * blockDim.x + threadIdx.x;
    if (e < N_EDGES) atomicAdd(&g_deg[eidx(ei, N_EDGES + e)], 1.0f);
}
__global__ void k_dis() {
    int i = blockIdx.x * blockDim.x + threadIdx.x;
    if (i < N_NODES) g_dis[i] = rsqrtf(g_deg[i]);  // deg >= 1 always
}

// ---------------- aggregation ----------------
__global__ void k_agg_init(const float* __restrict__ h, float* __restrict__ agg,
                           int D, int cshift) {
    int idx = blockIdx.x * blockDim.x + threadIdx.x;
    if (idx >= (N_NODES << cshift)) return;
    int i = idx >> cshift, c = idx & ((1 << cshift) - 1);
    float s = g_dis[i]; s *= s;
    float4 v = *(const float4*)&h[i * D + c * 4];
    v.x *= s; v.y *= s; v.z *= s; v.w *= s;
    *(float4*)&agg[i * D + c * 4] = v;
}
__global__ void k_agg_edges(const float* __restrict__ h, float* __restrict__ agg,
                            const void* __restrict__ ei, int D, int cshift) {
    int idx = blockIdx.x * blockDim.x + threadIdx.x;
    if (idx >= (N_EDGES << cshift)) return;
    int e = idx >> cshift, c = idx & ((1 << cshift) - 1);
    int r  = eidx(ei, e);
    int cl = eidx(ei, N_EDGES + e);
    float nrm = g_dis[r] * g_dis[cl];
    float4 v = *(const float4*)&h[r * D + c * 4];
    float* dst = &agg[cl * D + c * 4];
    atomicAdd(dst + 0, nrm * v.x);
    atomicAdd(dst + 1, nrm * v.y);
    atomicAdd(dst + 2, nrm * v.z);
    atomicAdd(dst + 3, nrm * v.w);
}

// ---------------- GCN GEMM + bias + ReLU + LayerNorm ----------------
__global__ void __launch_bounds__(256) k_gcn(
    const float* __restrict__ A, const float* __restrict__ W,
    const float* __restrict__ bias, const float* __restrict__ gam,
    const float* __restrict__ bet, float* __restrict__ out, int K)
{
    __shared__ float sA[16][16];
    __shared__ float sW[16][512];
    __shared__ float rsum[16][4], rsq[16][4];
    int t = threadIdx.x;
    int tx = t & 127, ty = t >> 7;
    int row0 = blockIdx.x * 16;
    unsigned long long a64[8][2];
#pragma unroll
    for (int j = 0; j < 8; j++) { a64[j][0] = 0ull; a64[j][1] = 0ull; }

    for (int k0 = 0; k0 < K; k0 += 16) {
        sA[t >> 4][t & 15] = A[(row0 + (t >> 4)) * K + k0 + (t & 15)];
#pragma unroll
        for (int i = 0; i < 8; i++) {
            int idx = t + i * 256;
            int kk = idx >> 7, c4 = idx & 127;
            *(float4*)&sW[kk][c4 * 4] = *(const float4*)&W[(k0 + kk) * 512 + c4 * 4];
        }
        __syncthreads();
#pragma unroll
        for (int kk = 0; kk < 16; kk++) {
            ulonglong2 w2 = *(ulonglong2*)&sW[kk][tx * 4];
#pragma unroll
            for (int j = 0; j < 8; j++) {
                unsigned long long aa = bcast2(sA[ty + j * 2][kk]);
                FMA2(a64[j][0], aa, w2.x);
                FMA2(a64[j][1], aa, w2.y);
            }
        }
        __syncthreads();
    }

    float acc[8][4];
#pragma unroll
    for (int j = 0; j < 8; j++) {
        unpack2(a64[j][0], acc[j][0], acc[j][1]);
        unpack2(a64[j][1], acc[j][2], acc[j][3]);
    }

    float4 b4 = *(const float4*)&bias[tx * 4];
    int lane = t & 31, quarter = (t >> 5) & 3;
#pragma unroll
    for (int j = 0; j < 8; j++) {
        acc[j][0] = fmaxf(acc[j][0] + b4.x, 0.f);
        acc[j][1] = fmaxf(acc[j][1] + b4.y, 0.f);
        acc[j][2] = fmaxf(acc[j][2] + b4.z, 0.f);
        acc[j][3] = fmaxf(acc[j][3] + b4.w, 0.f);
        int r = ty + j * 2;
        float s = acc[j][0] + acc[j][1] + acc[j][2] + acc[j][3];
        float q = acc[j][0]*acc[j][0] + acc[j][1]*acc[j][1]
                + acc[j][2]*acc[j][2] + acc[j][3]*acc[j][3];
        s = warp_sum(s); q = warp_sum(q);
        if (lane == 0) { rsum[r][quarter] = s; rsq[r][quarter] = q; }
    }
    __syncthreads();
    float4 g4  = *(const float4*)&gam[tx * 4];
    float4 be4 = *(const float4*)&bet[tx * 4];
#pragma unroll
    for (int j = 0; j < 8; j++) {
        int r = ty + j * 2;
        float s = rsum[r][0] + rsum[r][1] + rsum[r][2] + rsum[r][3];
        float q = rsq[r][0]  + rsq[r][1]  + rsq[r][2]  + rsq[r][3];
        float mu  = s * (1.f / 512.f);
        float var = q * (1.f / 512.f) - mu * mu;
        float rs  = rsqrtf(var + EPS);
        float4 o;
        o.x = (acc[j][0] - mu) * rs * g4.x + be4.x;
        o.y = (acc[j][1] - mu) * rs * g4.y + be4.y;
        o.z = (acc[j][2] - mu) * rs * g4.z + be4.z;
        o.w = (acc[j][3] - mu) * rs * g4.w + be4.w;
        *(float4*)&out[(row0 + r) * 512 + tx * 4] = o;
    }
}

// ---------------- tiled GEMM: C[N_PAD,1024] = Ain[N_PAD,512] @ W[512,1024] ----------------
__global__ void __launch_bounds__(256) k_gemm64(
    const float* __restrict__ Ain, const float* __restrict__ W, float* __restrict__ C)
{
    __shared__ float sA[64][20];
    __shared__ float sB[16][64];
    int t = threadIdx.x;
    int tx = t & 15, ty = t >> 4;
    int c0 = blockIdx.x * 64, r0 = blockIdx.y * 64;
    unsigned long long a64[4][2];
#pragma unroll
    for (int i = 0; i < 4; i++) { a64[i][0] = 0ull; a64[i][1] = 0ull; }

    for (int k0 = 0; k0 < 512; k0 += 16) {
        {
            int r = t >> 2, q = t & 3;
            *(float4*)&sA[r][q * 4] = *(const float4*)&Ain[(r0 + r) * 512 + k0 + q * 4];
        }
        {
            int kk = t >> 4, c4 = t & 15;
            *(float4*)&sB[kk][c4 * 4] = *(const float4*)&W[(size_t)(k0 + kk) * 1024 + c0 + c4 * 4];
        }
        __syncthreads();
#pragma unroll
        for (int kk = 0; kk < 16; kk++) {
            ulonglong2 b2 = *(ulonglong2*)&sB[kk][tx * 4];
#pragma unroll
            for (int i = 0; i < 4; i++) {
                unsigned long long aa = bcast2(sA[ty * 4 + i][kk]);
                FMA2(a64[i][0], aa, b2.x);
                FMA2(a64[i][1], aa, b2.y);
            }
        }
        __syncthreads();
    }
#pragma unroll
    for (int i = 0; i < 4; i++) {
        float4 o;
        unpack2(a64[i][0], o.x, o.y);
        unpack2(a64[i][1], o.z, o.w);
        *(float4*)&C[(size_t)(r0 + ty * 4 + i) * 1024 + c0 + tx * 4] = o;
    }
}

// ---------------- edge stage 1: Z[e] = relu(LN(A[s] + B[t] + mb0)) ----------------
__global__ void __launch_bounds__(256) k_edge1(
    const void* __restrict__ ei, const float* __restrict__ mb0,
    const float* __restrict__ g, const float* __restrict__ bt)
{
    int e = blockIdx.x;
    int t = threadIdx.x;
    int s = eidx(ei, e), d = eidx(ei, N_EDGES + e);
    float4 a = *(const float4*)&g_A[(size_t)s * 1024 + t * 4];
    float4 b = *(const float4*)&g_B[(size_t)d * 1024 + t * 4];
    float4 m = *(const float4*)&mb0[t * 4];
    float4 v;
    v.x = a.x + b.x + m.x; v.y = a.y + b.y + m.y;
    v.z = a.z + b.z + m.z; v.w = a.w + b.w + m.w;

    __shared__ float red[2][8];
    float sm = v.x + v.y + v.z + v.w;
    float sq = v.x*v.x + v.y*v.y + v.z*v.z + v.w*v.w;
    sm = warp_sum(sm); sq = warp_sum(sq);
    int warp = t >> 5, lane = t & 31;
    if (lane == 0) { red[0][warp] = sm; red[1][warp] = sq; }
    __syncthreads();
    float tot = 0.f, tot2 = 0.f;
#pragma unroll
    for (int w = 0; w < 8; w++) { tot += red[0][w]; tot2 += red[1][w]; }
    float mu  = tot * (1.f / 1024.f);
    float var = tot2 * (1.f / 1024.f) - mu * mu;
    float rs  = rsqrtf(var + EPS);
    float4 gg = *(const float4*)&g[t * 4];
    float4 bb = *(const float4*)&bt[t * 4];
    v.x = fmaxf((v.x - mu) * rs * gg.x + bb.x, 0.f);
    v.y = fmaxf((v.y - mu) * rs * gg.y + bb.y, 0.f);
    v.z = fmaxf((v.z - mu) * rs * gg.z + bb.z, 0.f);
    v.w = fmaxf((v.w - mu) * rs * gg.w + bb.w, 0.f);
    *(float4*)&g_Z[(size_t)e * 1024 + t * 4] = v;
}

// ---------------- edge stage 2 (TENSOR CORES, tf32) ----------------
// out = relu(LN(Z @ mw1 + mb1)) . mw2 + mb2
// 64 edges/block, 512 threads = 16 warps: 4 row-strips(16) x 4 col-strips(128).
// Each warp: 16 m16n8 tiles over K=1024 via mma.sync.m16n8k8.tf32.
__global__ void __launch_bounds__(512, 1) k_edge2(
    const float* __restrict__ W1, const float* __restrict__ mb1,
    const float* __restrict__ g, const float* __restrict__ bt,
    const float* __restrict__ mw2, const float* __restrict__ mb2,
    float* __restrict__ out)
{
    __shared__ unsigned sWu[16][520];   // stride 520: B-frag bank = 8*tig+g, conflict-free
    __shared__ unsigned sZu[64][20];    // stride 20: A-frag conflict-free
    __shared__ float ps[64][4], pq[64][4], pd[64][4];

    int t = threadIdx.x;
    int w = t >> 5, lane = t & 31;
    int gq = lane >> 2, tig = lane & 3;
    int row_half = w & 3, s = w >> 2;
    int lr0 = row_half * 16;
    int c0s = s * 128;
    int e0 = blockIdx.x * 64;

    float acc[16][4];
#pragma unroll
    for (int i = 0; i < 16; i++) { acc[i][0]=0.f; acc[i][1]=0.f; acc[i][2]=0.f; acc[i][3]=0.f; }

    for (int k0 = 0; k0 < 1024; k0 += 16) {
        // stage Z chunk [64 rows x 16 k], tf32-converted
        {
            int row = t >> 3, kk = (t & 7) * 2;
            float2 z2 = *(const float2*)&g_Z[(size_t)(e0 + row) * 1024 + k0 + kk];
            sZu[row][kk]     = tf32cvt(z2.x);
            sZu[row][kk + 1] = tf32cvt(z2.y);
        }
        // stage W chunk [16 k x 512 n], tf32-converted
#pragma unroll
        for (int i = 0; i < 4; i++) {
            int vi = t + i * 512;
            int kk = vi >> 7, c4 = vi & 127;
            float4 w4 = *(const float4*)&W1[(size_t)(k0 + kk) * 512 + c4 * 4];
            unsigned* p = &sWu[kk][c4 * 4];
            p[0] = tf32cvt(w4.x); p[1] = tf32cvt(w4.y);
            p[2] = tf32cvt(w4.z); p[3] = tf32cvt(w4.w);
        }
        __syncthreads();
#pragma unroll
        for (int k8 = 0; k8 < 16; k8 += 8) {
            unsigned a0 = sZu[lr0 + gq    ][k8 + tig];
            unsigned a1 = sZu[lr0 + gq + 8][k8 + tig];
            unsigned a2 = sZu[lr0 + gq    ][k8 + tig + 4];
            unsigned a3 = sZu[lr0 + gq + 8][k8 + tig + 4];
#pragma unroll
            for (int i = 0; i < 16; i++) {
                unsigned b0 = sWu[k8 + tig    ][c0s + i * 8 + gq];
                unsigned b1 = sWu[k8 + tig + 4][c0s + i * 8 + gq];
                mma_tf32(acc[i], a0, a1, a2, a3, b0, b1);
            }
        }
        __syncthreads();
    }

    // rows this lane owns: rA = lr0+gq (acc[.][0],[1]), rB = rA+8 (acc[.][2],[3])
    int rA = lr0 + gq, rB = rA + 8;

    // bias + partial sums
    float sA = 0.f, qA = 0.f, sB = 0.f, qB = 0.f;
#pragma unroll
    for (int i = 0; i < 16; i++) {
        int col = c0s + i * 8 + 2 * tig;
        float2 b2 = *(const float2*)&mb1[col];
        acc[i][0] += b2.x; acc[i][1] += b2.y;
        acc[i][2] += b2.x; acc[i][3] += b2.y;
        sA += acc[i][0] + acc[i][1];
        qA += acc[i][0]*acc[i][0] + acc[i][1]*acc[i][1];
        sB += acc[i][2] + acc[i][3];
        qB += acc[i][2]*acc[i][2] + acc[i][3]*acc[i][3];
    }
#pragma unroll
    for (int o = 1; o <= 2; o <<= 1) {
        sA += __shfl_xor_sync(0xffffffffu, sA, o);
        qA += __shfl_xor_sync(0xffffffffu, qA, o);
        sB += __shfl_xor_sync(0xffffffffu, sB, o);
        qB += __shfl_xor_sync(0xffffffffu, qB, o);
    }
    if (tig == 0) { ps[rA][s] = sA; pq[rA][s] = qA; ps[rB][s] = sB; pq[rB][s] = qB; }
    __syncthreads();

    float SA = ps[rA][0] + ps[rA][1] + ps[rA][2] + ps[rA][3];
    float QA = pq[rA][0] + pq[rA][1] + pq[rA][2] + pq[rA][3];
    float SB = ps[rB][0] + ps[rB][1] + ps[rB][2] + ps[rB][3];
    float QB = pq[rB][0] + pq[rB][1] + pq[rB][2] + pq[rB][3];
    float muA = SA * (1.f / 512.f);
    float rsA = rsqrtf(QA * (1.f / 512.f) - muA * muA + EPS);
    float muB = SB * (1.f / 512.f);
    float rsB = rsqrtf(QB * (1.f / 512.f) - muB * muB + EPS);

    float dA = 0.f, dB = 0.f;
#pragma unroll
    for (int i = 0; i < 16; i++) {
        int col = c0s + i * 8 + 2 * tig;
        float2 gm = *(const float2*)&g[col];
        float2 bb = *(const float2*)&bt[col];
        float2 w2 = *(const float2*)&mw2[col];
        dA += fmaxf((acc[i][0] - muA) * rsA * gm.x + bb.x, 0.f) * w2.x
            + fmaxf((acc[i][1] - muA) * rsA * gm.y + bb.y, 0.f) * w2.y;
        dB += fmaxf((acc[i][2] - muB) * rsB * gm.x + bb.x, 0.f) * w2.x
            + fmaxf((acc[i][3] - muB) * rsB * gm.y + bb.y, 0.f) * w2.y;
    }
#pragma unroll
    for (int o = 1; o <= 2; o <<= 1) {
        dA += __shfl_xor_sync(0xffffffffu, dA, o);
        dB += __shfl_xor_sync(0xffffffffu, dB, o);
    }
    if (tig == 0) { pd[rA][s] = dA; pd[rB][s] = dB; }
    __syncthreads();

    if (t < 64)
        out[e0 + t] = pd[t][0] + pd[t][1] + pd[t][2] + pd[t][3] + mb2[0];
}

// ---------------- launch ----------------
extern "C" void kernel_launch(void* const* d_in, const int* in_sizes, int n_in,
                              void* d_out, int out_size)
{
    const float* x    = (const float*)d_in[0];
    const void*  ei   = d_in[1];                  // int32 or int64, detected on device
    const float* w0   = (const float*)d_in[2];
    const float* b0   = (const float*)d_in[3];
    const float* ws   = (const float*)d_in[4];
    const float* bs   = (const float*)d_in[5];
    const float* lng  = (const float*)d_in[6];
    const float* lnb  = (const float*)d_in[7];
    const float* mw0  = (const float*)d_in[8];
    const float* mb0  = (const float*)d_in[9];
    const float* mg0  = (const float*)d_in[10];
    const float* mbt0 = (const float*)d_in[11];
    const float* mw1  = (const float*)d_in[12];
    const float* mb1  = (const float*)d_in[13];
    const float* mg1  = (const float*)d_in[14];
    const float* mbt1 = (const float*)d_in[15];
    const float* mw2  = (const float*)d_in[16];
    const float* mb2  = (const float*)d_in[17];
    float* out = (float*)d_out;

    float *p_agg, *p_h, *p_A, *p_B;
    cudaGetSymbolAddress((void**)&p_agg, g_agg);
    cudaGetSymbolAddress((void**)&p_h,   g_h);
    cudaGetSymbolAddress((void**)&p_A,   g_A);
    cudaGetSymbolAddress((void**)&p_B,   g_B);

    // dtype detection + normalization
    k_detect<<<1, 32>>>((const int*)ei);
    k_deg_zero<<<(N_NODES + 255) / 256, 256>>>();
    k_deg_acc <<<(N_EDGES + 255) / 256, 256>>>(ei);
    k_dis     <<<(N_NODES + 255) / 256, 256>>>();

    // layer 0 (aggregate in 128-dim input space, then GEMM 128->512)
    k_agg_init <<<(N_NODES * 32 + 255) / 256, 256>>>(x, p_agg, 128, 5);
    k_agg_edges<<<(N_EDGES * 32 + 255) / 256, 256>>>(x, p_agg, ei, 128, 5);
    k_gcn<<<N_NODES / 16, 256>>>(p_agg, w0, b0, lng, lnb, p_h, 128);

    // layers 1..3
    for (int i = 1; i < 4; i++) {
        k_agg_init <<<(N_NODES * 128 + 255) / 256, 256>>>(p_h, p_agg, 512, 7);
        k_agg_edges<<<(N_EDGES * 128 + 255) / 256, 256>>>(p_h, p_agg, ei, 512, 7);
        k_gcn<<<N_NODES / 16, 256>>>(p_agg, ws + (size_t)(i - 1) * 512 * 512,
                                     bs + (i - 1) * 512, lng + i * 512, lnb + i * 512,
                                     p_h, 512);
    }

    // edge MLP first layer factored per-node: A = h @ mw0[:512], B = h @ mw0[512:]
    dim3 gAB(16, N_PAD / 64);
    k_gemm64<<<gAB, 256>>>(p_h, mw0, p_A);
    k_gemm64<<<gAB, 256>>>(p_h, mw0 + (size_t)512 * 1024, p_B);

    // per-edge: z = relu(LN(A[s]+B[t]+mb0))
    k_edge1<<<N_EDGES, 256>>>(ei, mb0, mg0, mbt0);

    // z @ mw1 + LN + relu + dot(mw2) + mb2  (fused, tensor cores)
    k_edge2<<<N_EDGES / 64, 512>>>(mw1, mb1, mg1, mbt1, mw2, mb2, out);
}

// round 8
// speedup vs baseline: 1.8178x; 1.7364x over previous
#include <cuda_runtime.h>

#define N_NODES 10000
#define N_PAD   10048
#define N_EDGES 160000
#define HID     512
#define EPS     1e-5f

// ---------------- scratch (static __device__, allowed) ----------------
__device__ float g_dis[N_NODES];
__device__ int   g_cnt[N_NODES];
__device__ int   g_rowptr[N_NODES + 1];
__device__ int   g_cur[N_NODES];
__device__ int   g_src[N_EDGES];
__device__ float g_nrm[N_EDGES];
__device__ float g_agg[N_PAD * HID];
__device__ float g_h  [N_PAD * HID];
__device__ float g_A  [N_PAD * 1024];
__device__ float g_B  [N_PAD * 1024];
__device__ float g_Z  [(size_t)N_EDGES * 1024];   // 640 MB
__device__ int   g_is64;

__device__ __forceinline__ float warp_sum(float v) {
#pragma unroll
    for (int o = 16; o > 0; o >>= 1) v += __shfl_xor_sync(0xffffffffu, v, o);
    return v;
}

// ---- packed fp32x2 FMA ----
#define FMA2(d, a, b) asm("fma.rn.f32x2 %0, %1, %2, %0;" : "+l"(d) : "l"(a), "l"(b))
__device__ __forceinline__ unsigned long long bcast2(float a) {
    unsigned long long r;
    asm("mov.b64 %0, {%1, %1};" : "=l"(r) : "f"(a));
    return r;
}
__device__ __forceinline__ void unpack2(unsigned long long d, float& lo, float& hi) {
    asm("mov.b64 {%0, %1}, %2;" : "=f"(lo), "=f"(hi) : "l"(d));
}

// ---- tf32 helpers ----
__device__ __forceinline__ unsigned tf32cvt(float f) {
    unsigned u; asm("cvt.rna.tf32.f32 %0, %1;" : "=r"(u) : "f"(f)); return u;
}
__device__ __forceinline__ void mma_tf32(float* c,
    unsigned a0, unsigned a1, unsigned a2, unsigned a3,
    unsigned b0, unsigned b1)
{
    asm volatile(
        "mma.sync.aligned.m16n8k8.row.col.f32.tf32.tf32.f32 "
        "{%0,%1,%2,%3}, {%4,%5,%6,%7}, {%8,%9}, {%0,%1,%2,%3};"
        : "+f"(c[0]), "+f"(c[1]), "+f"(c[2]), "+f"(c[3])
        : "r"(a0), "r"(a1), "r"(a2), "r"(a3), "r"(b0), "r"(b1));
}

// edge_index may be int32 (JAX default) or int64; g_is64 selects.
__device__ __forceinline__ int eidx(const void* __restrict__ ei, int pos) {
    return g_is64 ? (int)((const long long*)ei)[pos] : ((const int*)ei)[pos];
}

// ---------------- dtype detection ----------------
__global__ void k_detect(const int* __restrict__ ei32) {
    if (threadIdx.x == 0) {
        int all0 = 1;
        for (int i = 0; i < 1000; i++)
            if (ei32[2 * i + 1] != 0) { all0 = 0; break; }
        g_is64 = all0;
    }
}

// ---------------- CSR build ----------------
__global__ void k_cnt_zero() {
    int i = blockIdx.x * blockDim.x + threadIdx.x;
    if (i < N_NODES) g_cnt[i] = 0;
}
__global__ void k_cnt_acc(const void* __restrict__ ei) {
    int e = blockIdx.x * blockDim.x + threadIdx.x;
    if (e < N_EDGES) atomicAdd(&g_cnt[eidx(ei, N_EDGES + e)], 1);
}
// one-block exclusive scan over 10000 counts -> rowptr, cursor; also dis = rsqrt(cnt+1)
#define SCAN_T 1024
#define SCAN_C 10
__global__ void __launch_bounds__(SCAN_T) k_scan() {
    __shared__ int part[SCAN_T];
    int t = threadIdx.x;
    int base = t * SCAN_C;
    int loc[SCAN_C];
    int s = 0;
#pragma unroll
    for (int i = 0; i < SCAN_C; i++) {
        int n = base + i;
        int c = (n < N_NODES) ? g_cnt[n] : 0;
        loc[i] = s; s += c;
    }
    part[t] = s;
    __syncthreads();
    for (int off = 1; off < SCAN_T; off <<= 1) {
        int v = (t >= off) ? part[t - off] : 0;
        __syncthreads();
        part[t] += v;
        __syncthreads();
    }
    int pre = (t > 0) ? part[t - 1] : 0;
#pragma unroll
    for (int i = 0; i < SCAN_C; i++) {
        int n = base + i;
        if (n < N_NODES) {
            int p = pre + loc[i];
            g_rowptr[n] = p;
            g_cur[n]    = p;
            g_dis[n]    = rsqrtf((float)g_cnt[n] + 1.0f);  // +1 self-loop
        }
    }
    if (t == SCAN_T - 1) g_rowptr[N_NODES] = part[t];
}
__global__ void k_fill(const void* __restrict__ ei) {
    int e = blockIdx.x * blockDim.x + threadIdx.x;
    if (e >= N_EDGES) return;
    int r = eidx(ei, e);
    int c = eidx(ei, N_EDGES + e);
    int p = atomicAdd(&g_cur[c], 1);
    g_src[p] = r;
    g_nrm[p] = g_dis[r] * g_dis[c];
}

// ---------------- aggregation: pure gather via CSR (no atomics) ----------------
// block = target node, 128 threads over D columns.
__global__ void __launch_bounds__(128) k_gather512(const float* __restrict__ h,
                                                   float* __restrict__ agg) {
    int v = blockIdx.x;
    int t = threadIdx.x;
    int b = g_rowptr[v], e = g_rowptr[v + 1];
    float s = g_dis[v]; s *= s;
    float4 hv = *(const float4*)&h[(size_t)v * 512 + t * 4];
    float4 acc;
    acc.x = s * hv.x; acc.y = s * hv.y; acc.z = s * hv.z; acc.w = s * hv.w;
    for (int j = b; j < e; j++) {
        int   src = g_src[j];
        float nr  = g_nrm[j];
        float4 x = *(const float4*)&h[(size_t)src * 512 + t * 4];
        acc.x += nr * x.x; acc.y += nr * x.y;
        acc.z += nr * x.z; acc.w += nr * x.w;
    }
    *(float4*)&agg[(size_t)v * 512 + t * 4] = acc;
}
__global__ void __launch_bounds__(128) k_gather128(const float* __restrict__ h,
                                                   float* __restrict__ agg) {
    int v = blockIdx.x;
    int t = threadIdx.x;
    int b = g_rowptr[v], e = g_rowptr[v + 1];
    float s = g_dis[v]; s *= s;
    float acc = s * h[(size_t)v * 128 + t];
    for (int j = b; j < e; j++)
        acc += g_nrm[j] * h[(size_t)g_src[j] * 128 + t];
    agg[(size_t)v * 128 + t] = acc;
}

// ---------------- GCN GEMM + bias + ReLU + LayerNorm ----------------
__global__ void __launch_bounds__(256) k_gcn(
    const float* __restrict__ A, const float* __restrict__ W,
    const float* __restrict__ bias, const float* __restrict__ gam,
    const float* __restrict__ bet, float* __restrict__ out, int K)
{
    __shared__ float sA[16][16];
    __shared__ float sW[16][512];
    __shared__ float rsum[16][4], rsq[16][4];
    int t = threadIdx.x;
    int tx = t & 127, ty = t >> 7;
    int row0 = blockIdx.x * 16;
    unsigned long long a64[8][2];
#pragma unroll
    for (int j = 0; j < 8; j++) { a64[j][0] = 0ull; a64[j][1] = 0ull; }

    for (int k0 = 0; k0 < K; k0 += 16) {
        sA[t >> 4][t & 15] = A[(row0 + (t >> 4)) * K + k0 + (t & 15)];
#pragma unroll
        for (int i = 0; i < 8; i++) {
            int idx = t + i * 256;
            int kk = idx >> 7, c4 = idx & 127;
            *(float4*)&sW[kk][c4 * 4] = *(const float4*)&W[(k0 + kk) * 512 + c4 * 4];
        }
        __syncthreads();
#pragma unroll
        for (int kk = 0; kk < 16; kk++) {
            ulonglong2 w2 = *(ulonglong2*)&sW[kk][tx * 4];
#pragma unroll
            for (int j = 0; j < 8; j++) {
                unsigned long long aa = bcast2(sA[ty + j * 2][kk]);
                FMA2(a64[j][0], aa, w2.x);
                FMA2(a64[j][1], aa, w2.y);
            }
        }
        __syncthreads();
    }

    float acc[8][4];
#pragma unroll
    for (int j = 0; j < 8; j++) {
        unpack2(a64[j][0], acc[j][0], acc[j][1]);
        unpack2(a64[j][1], acc[j][2], acc[j][3]);
    }

    float4 b4 = *(const float4*)&bias[tx * 4];
    int lane = t & 31, quarter = (t >> 5) & 3;
#pragma unroll
    for (int j = 0; j < 8; j++) {
        acc[j][0] = fmaxf(acc[j][0] + b4.x, 0.f);
        acc[j][1] = fmaxf(acc[j][1] + b4.y, 0.f);
        acc[j][2] = fmaxf(acc[j][2] + b4.z, 0.f);
        acc[j][3] = fmaxf(acc[j][3] + b4.w, 0.f);
        int r = ty + j * 2;
        float s = acc[j][0] + acc[j][1] + acc[j][2] + acc[j][3];
        float q = acc[j][0]*acc[j][0] + acc[j][1]*acc[j][1]
                + acc[j][2]*acc[j][2] + acc[j][3]*acc[j][3];
        s = warp_sum(s); q = warp_sum(q);
        if (lane == 0) { rsum[r][quarter] = s; rsq[r][quarter] = q; }
    }
    __syncthreads();
    float4 g4  = *(const float4*)&gam[tx * 4];
    float4 be4 = *(const float4*)&bet[tx * 4];
#pragma unroll
    for (int j = 0; j < 8; j++) {
        int r = ty + j * 2;
        float s = rsum[r][0] + rsum[r][1] + rsum[r][2] + rsum[r][3];
        float q = rsq[r][0]  + rsq[r][1]  + rsq[r][2]  + rsq[r][3];
        float mu  = s * (1.f / 512.f);
        float var = q * (1.f / 512.f) - mu * mu;
        float rs  = rsqrtf(var + EPS);
        float4 o;
        o.x = (acc[j][0] - mu) * rs * g4.x + be4.x;
        o.y = (acc[j][1] - mu) * rs * g4.y + be4.y;
        o.z = (acc[j][2] - mu) * rs * g4.z + be4.z;
        o.w = (acc[j][3] - mu) * rs * g4.w + be4.w;
        *(float4*)&out[(row0 + r) * 512 + tx * 4] = o;
    }
}

// ---------------- tiled GEMM: C[N_PAD,1024] = Ain[N_PAD,512] @ W[512,1024] ----------------
__global__ void __launch_bounds__(256) k_gemm64(
    const float* __restrict__ Ain, const float* __restrict__ W, float* __restrict__ C)
{
    __shared__ float sA[64][20];
    __shared__ float sB[16][64];
    int t = threadIdx.x;
    int tx = t & 15, ty = t >> 4;
    int c0 = blockIdx.x * 64, r0 = blockIdx.y * 64;
    unsigned long long a64[4][2];
#pragma unroll
    for (int i = 0; i < 4; i++) { a64[i][0] = 0ull; a64[i][1] = 0ull; }

    for (int k0 = 0; k0 < 512; k0 += 16) {
        {
            int r = t >> 2, q = t & 3;
            *(float4*)&sA[r][q * 4] = *(const float4*)&Ain[(r0 + r) * 512 + k0 + q * 4];
        }
        {
            int kk = t >> 4, c4 = t & 15;
            *(float4*)&sB[kk][c4 * 4] = *(const float4*)&W[(size_t)(k0 + kk) * 1024 + c0 + c4 * 4];
        }
        __syncthreads();
#pragma unroll
        for (int kk = 0; kk < 16; kk++) {
            ulonglong2 b2 = *(ulonglong2*)&sB[kk][tx * 4];
#pragma unroll
            for (int i = 0; i < 4; i++) {
                unsigned long long aa = bcast2(sA[ty * 4 + i][kk]);
                FMA2(a64[i][0], aa, b2.x);
                FMA2(a64[i][1], aa, b2.y);
            }
        }
        __syncthreads();
    }
#pragma unroll
    for (int i = 0; i < 4; i++) {
        float4 o;
        unpack2(a64[i][0], o.x, o.y);
        unpack2(a64[i][1], o.z, o.w);
        *(float4*)&C[(size_t)(r0 + ty * 4 + i) * 1024 + c0 + tx * 4] = o;
    }
}

// ---------------- edge stage 1: Z[e] = relu(LN(A[s] + B[t] + mb0)) ----------------
__global__ void __launch_bounds__(256) k_edge1(
    const void* __restrict__ ei, const float* __restrict__ mb0,
    const float* __restrict__ g, const float* __restrict__ bt)
{
    int e = blockIdx.x;
    int t = threadIdx.x;
    int s = eidx(ei, e), d = eidx(ei, N_EDGES + e);
    float4 a = *(const float4*)&g_A[(size_t)s * 1024 + t * 4];
    float4 b = *(const float4*)&g_B[(size_t)d * 1024 + t * 4];
    float4 m = *(const float4*)&mb0[t * 4];
    float4 v;
    v.x = a.x + b.x + m.x; v.y = a.y + b.y + m.y;
    v.z = a.z + b.z + m.z; v.w = a.w + b.w + m.w;

    __shared__ float red[2][8];
    float sm = v.x + v.y + v.z + v.w;
    float sq = v.x*v.x + v.y*v.y + v.z*v.z + v.w*v.w;
    sm = warp_sum(sm); sq = warp_sum(sq);
    int warp = t >> 5, lane = t & 31;
    if (lane == 0) { red[0][warp] = sm; red[1][warp] = sq; }
    __syncthreads();
    float tot = 0.f, tot2 = 0.f;
#pragma unroll
    for (int w = 0; w < 8; w++) { tot += red[0][w]; tot2 += red[1][w]; }
    float mu  = tot * (1.f / 1024.f);
    float var = tot2 * (1.f / 1024.f) - mu * mu;
    float rs  = rsqrtf(var + EPS);
    float4 gg = *(const float4*)&g[t * 4];
    float4 bb = *(const float4*)&bt[t * 4];
    v.x = fmaxf((v.x - mu) * rs * gg.x + bb.x, 0.f);
    v.y = fmaxf((v.y - mu) * rs * gg.y + bb.y, 0.f);
    v.z = fmaxf((v.z - mu) * rs * gg.z + bb.z, 0.f);
    v.w = fmaxf((v.w - mu) * rs * gg.w + bb.w, 0.f);
    *(float4*)&g_Z[(size_t)e * 1024 + t * 4] = v;
}

// ---------------- edge stage 2 (TENSOR CORES, tf32) ----------------
__global__ void __launch_bounds__(512, 1) k_edge2(
    const float* __restrict__ W1, const float* __restrict__ mb1,
    const float* __restrict__ g, const float* __restrict__ bt,
    const float* __restrict__ mw2, const float* __restrict__ mb2,
    float* __restrict__ out)
{
    __shared__ unsigned sWu[16][520];
    __shared__ unsigned sZu[64][20];
    __shared__ float ps[64][4], pq[64][4], pd[64][4];

    int t = threadIdx.x;
    int w = t >> 5, lane = t & 31;
    int gq = lane >> 2, tig = lane & 3;
    int row_half = w & 3, s = w >> 2;
    int lr0 = row_half * 16;
    int c0s = s * 128;
    int e0 = blockIdx.x * 64;

    float acc[16][4];
#pragma unroll
    for (int i = 0; i < 16; i++) { acc[i][0]=0.f; acc[i][1]=0.f; acc[i][2]=0.f; acc[i][3]=0.f; }

    for (int k0 = 0; k0 < 1024; k0 += 16) {
        {
            int row = t >> 3, kk = (t & 7) * 2;
            float2 z2 = *(const float2*)&g_Z[(size_t)(e0 + row) * 1024 + k0 + kk];
            sZu[row][kk]     = tf32cvt(z2.x);
            sZu[row][kk + 1] = tf32cvt(z2.y);
        }
#pragma unroll
        for (int i = 0; i < 4; i++) {
            int vi = t + i * 512;
            int kk = vi >> 7, c4 = vi & 127;
            float4 w4 = *(const float4*)&W1[(size_t)(k0 + kk) * 512 + c4 * 4];
            unsigned* p = &sWu[kk][c4 * 4];
            p[0] = tf32cvt(w4.x); p[1] = tf32cvt(w4.y);
            p[2] = tf32cvt(w4.z); p[3] = tf32cvt(w4.w);
        }
        __syncthreads();
#pragma unroll
        for (int k8 = 0; k8 < 16; k8 += 8) {
            unsigned a0 = sZu[lr0 + gq    ][k8 + tig];
            unsigned a1 = sZu[lr0 + gq + 8][k8 + tig];
            unsigned a2 = sZu[lr0 + gq    ][k8 + tig + 4];
            unsigned a3 = sZu[lr0 + gq + 8][k8 + tig + 4];
#pragma unroll
            for (int i = 0; i < 16; i++) {
                unsigned b0 = sWu[k8 + tig    ][c0s + i * 8 + gq];
                unsigned b1 = sWu[k8 + tig + 4][c0s + i * 8 + gq];
                mma_tf32(acc[i], a0, a1, a2, a3, b0, b1);
            }
        }
        __syncthreads();
    }

    int rA = lr0 + gq, rB = rA + 8;

    float sA = 0.f, qA = 0.f, sB = 0.f, qB = 0.f;
#pragma unroll
    for (int i = 0; i < 16; i++) {
        int col = c0s + i * 8 + 2 * tig;
        float2 b2 = *(const float2*)&mb1[col];
        acc[i][0] += b2.x; acc[i][1] += b2.y;
        acc[i][2] += b2.x; acc[i][3] += b2.y;
        sA += acc[i][0] + acc[i][1];
        qA += acc[i][0]*acc[i][0] + acc[i][1]*acc[i][1];
        sB += acc[i][2] + acc[i][3];
        qB += acc[i][2]*acc[i][2] + acc[i][3]*acc[i][3];
    }
#pragma unroll
    for (int o = 1; o <= 2; o <<= 1) {
        sA += __shfl_xor_sync(0xffffffffu, sA, o);
        qA += __shfl_xor_sync(0xffffffffu, qA, o);
        sB += __shfl_xor_sync(0xffffffffu, sB, o);
        qB += __shfl_xor_sync(0xffffffffu, qB, o);
    }
    if (tig == 0) { ps[rA][s] = sA; pq[rA][s] = qA; ps[rB][s] = sB; pq[rB][s] = qB; }
    __syncthreads();

    float SA = ps[rA][0] + ps[rA][1] + ps[rA][2] + ps[rA][3];
    float QA = pq[rA][0] + pq[rA][1] + pq[rA][2] + pq[rA][3];
    float SB = ps[rB][0] + ps[rB][1] + ps[rB][2] + ps[rB][3];
    float QB = pq[rB][0] + pq[rB][1] + pq[rB][2] + pq[rB][3];
    float muA = SA * (1.f / 512.f);
    float rsA = rsqrtf(QA * (1.f / 512.f) - muA * muA + EPS);
    float muB = SB * (1.f / 512.f);
    float rsB = rsqrtf(QB * (1.f / 512.f) - muB * muB + EPS);

    float dA = 0.f, dB = 0.f;
#pragma unroll
    for (int i = 0; i < 16; i++) {
        int col = c0s + i * 8 + 2 * tig;
        float2 gm = *(const float2*)&g[col];
        float2 bb = *(const float2*)&bt[col];
        float2 w2 = *(const float2*)&mw2[col];
        dA += fmaxf((acc[i][0] - muA) * rsA * gm.x + bb.x, 0.f) * w2.x
            + fmaxf((acc[i][1] - muA) * rsA * gm.y + bb.y, 0.f) * w2.y;
        dB += fmaxf((acc[i][2] - muB) * rsB * gm.x + bb.x, 0.f) * w2.x
            + fmaxf((acc[i][3] - muB) * rsB * gm.y + bb.y, 0.f) * w2.y;
    }
#pragma unroll
    for (int o = 1; o <= 2; o <<= 1) {
        dA += __shfl_xor_sync(0xffffffffu, dA, o);
        dB += __shfl_xor_sync(0xffffffffu, dB, o);
    }
    if (tig == 0) { pd[rA][s] = dA; pd[rB][s] = dB; }
    __syncthreads();

    if (t < 64)
        out[e0 + t] = pd[t][0] + pd[t][1] + pd[t][2] + pd[t][3] + mb2[0];
}

// ---------------- launch ----------------
extern "C" void kernel_launch(void* const* d_in, const int* in_sizes, int n_in,
                              void* d_out, int out_size)
{
    const float* x    = (const float*)d_in[0];
    const void*  ei   = d_in[1];
    const float* w0   = (const float*)d_in[2];
    const float* b0   = (const float*)d_in[3];
    const float* ws   = (const float*)d_in[4];
    const float* bs   = (const float*)d_in[5];
    const float* lng  = (const float*)d_in[6];
    const float* lnb  = (const float*)d_in[7];
    const float* mw0  = (const float*)d_in[8];
    const float* mb0  = (const float*)d_in[9];
    const float* mg0  = (const float*)d_in[10];
    const float* mbt0 = (const float*)d_in[11];
    const float* mw1  = (const float*)d_in[12];
    const float* mb1  = (const float*)d_in[13];
    const float* mg1  = (const float*)d_in[14];
    const float* mbt1 = (const float*)d_in[15];
    const float* mw2  = (const float*)d_in[16];
    const float* mb2  = (const float*)d_in[17];
    float* out = (float*)d_out;

    float *p_agg, *p_h, *p_A, *p_B;
    cudaGetSymbolAddress((void**)&p_agg, g_agg);
    cudaGetSymbolAddress((void**)&p_h,   g_h);
    cudaGetSymbolAddress((void**)&p_A,   g_A);
    cudaGetSymbolAddress((void**)&p_B,   g_B);

    // dtype detect + CSR build (degree, scan, dis, fill)
    k_detect<<<1, 32>>>((const int*)ei);
    k_cnt_zero<<<(N_NODES + 255) / 256, 256>>>();
    k_cnt_acc <<<(N_EDGES + 255) / 256, 256>>>(ei);
    k_scan<<<1, SCAN_T>>>();
    k_fill<<<(N_EDGES + 255) / 256, 256>>>(ei);

    // layer 0 (aggregate in 128-dim input space, then GEMM 128->512)
    k_gather128<<<N_NODES, 128>>>(x, p_agg);
    k_gcn<<<N_NODES / 16, 256>>>(p_agg, w0, b0, lng, lnb, p_h, 128);

    // layers 1..3
    for (int i = 1; i < 4; i++) {
        k_gather512<<<N_NODES, 128>>>(p_h, p_agg);
        k_gcn<<<N_NODES / 16, 256>>>(p_agg, ws + (size_t)(i - 1) * 512 * 512,
                                     bs + (i - 1) * 512, lng + i * 512, lnb + i * 512,
                                     p_h, 512);
    }

    // edge MLP first layer factored per-node: A = h @ mw0[:512], B = h @ mw0[512:]
    dim3 gAB(16, N_PAD / 64);
    k_gemm64<<<gAB, 256>>>(p_h, mw0, p_A);
    k_gemm64<<<gAB, 256>>>(p_h, mw0 + (size_t)512 * 1024, p_B);

    // per-edge: z = relu(LN(A[s]+B[t]+mb0))
    k_edge1<<<N_EDGES, 256>>>(ei, mb0, mg0, mbt0);

    // z @ mw1 + LN + relu + dot(mw2) + mb2  (fused, tensor cores)
    k_edge2<<<N_EDGES / 64, 512>>>(mw1, mb1, mg1, mbt1, mw2, mb2, out);
}

// round 13
// speedup vs baseline: 2.0384x; 1.1214x over previous
#include <cuda_runtime.h>

#define N_NODES 10000
#define N_PAD   10048
#define N_EDGES 160000
#define HID     512
#define EPS     1e-5f

// ---------------- scratch (static __device__, allowed) ----------------
__device__ float g_dis[N_NODES];
__device__ int   g_cnt[N_NODES];
__device__ int   g_rowptr[N_NODES + 1];
__device__ int   g_cur[N_NODES];
__device__ int   g_src[N_EDGES];
__device__ float g_nrm[N_EDGES];
__device__ float g_agg[N_PAD * HID];
__device__ float g_h  [N_PAD * HID];
__device__ float g_A  [N_PAD * 1024];
__device__ float g_B  [N_PAD * 1024];
__device__ unsigned g_W1t[1024 * 512];   // mw1 pre-converted to tf32
__device__ int   g_is64;

__device__ __forceinline__ float warp_sum(float v) {
#pragma unroll
    for (int o = 16; o > 0; o >>= 1) v += __shfl_xor_sync(0xffffffffu, v, o);
    return v;
}

// ---- packed fp32x2 FMA ----
#define FMA2(d, a, b) asm("fma.rn.f32x2 %0, %1, %2, %0;" : "+l"(d) : "l"(a), "l"(b))
__device__ __forceinline__ unsigned long long bcast2(float a) {
    unsigned long long r;
    asm("mov.b64 %0, {%1, %1};" : "=l"(r) : "f"(a));
    return r;
}
__device__ __forceinline__ void unpack2(unsigned long long d, float& lo, float& hi) {
    asm("mov.b64 {%0, %1}, %2;" : "=f"(lo), "=f"(hi) : "l"(d));
}

// ---- tf32 helpers ----
__device__ __forceinline__ unsigned tf32cvt(float f) {
    unsigned u; asm("cvt.rna.tf32.f32 %0, %1;" : "=r"(u) : "f"(f)); return u;
}
__device__ __forceinline__ void mma_tf32(float* c,
    unsigned a0, unsigned a1, unsigned a2, unsigned a3,
    unsigned b0, unsigned b1)
{
    asm volatile(
        "mma.sync.aligned.m16n8k8.row.col.f32.tf32.tf32.f32 "
        "{%0,%1,%2,%3}, {%4,%5,%6,%7}, {%8,%9}, {%0,%1,%2,%3};"
        : "+f"(c[0]), "+f"(c[1]), "+f"(c[2]), "+f"(c[3])
        : "r"(a0), "r"(a1), "r"(a2), "r"(a3), "r"(b0), "r"(b1));
}

// edge_index may be int32 (JAX default) or int64; g_is64 selects.
__device__ __forceinline__ int eidx(const void* __restrict__ ei, int pos) {
    return g_is64 ? (int)((const long long*)ei)[pos] : ((const int*)ei)[pos];
}

// ---------------- dtype detection ----------------
__global__ void k_detect(const int* __restrict__ ei32) {
    if (threadIdx.x == 0) {
        int all0 = 1;
        for (int i = 0; i < 1000; i++)
            if (ei32[2 * i + 1] != 0) { all0 = 0; break; }
        g_is64 = all0;
    }
}

// ---------------- W1 pre-convert to tf32 ----------------
__global__ void k_w1cvt(const float* __restrict__ W1) {
    int i = (blockIdx.x * blockDim.x + threadIdx.x) * 4;
    float4 w4 = *(const float4*)&W1[i];
    uint4 o;
    o.x = tf32cvt(w4.x); o.y = tf32cvt(w4.y);
    o.z = tf32cvt(w4.z); o.w = tf32cvt(w4.w);
    *(uint4*)&g_W1t[i] = o;
}

// ---------------- CSR build ----------------
__global__ void k_cnt_zero() {
    int i = blockIdx.x * blockDim.x + threadIdx.x;
    if (i < N_NODES) g_cnt[i] = 0;
}
__global__ void k_cnt_acc(const void* __restrict__ ei) {
    int e = blockIdx.x * blockDim.x + threadIdx.x;
    if (e < N_EDGES) atomicAdd(&g_cnt[eidx(ei, N_EDGES + e)], 1);
}
#define SCAN_T 1024
#define SCAN_C 10
__global__ void __launch_bounds__(SCAN_T) k_scan() {
    __shared__ int part[SCAN_T];
    int t = threadIdx.x;
    int base = t * SCAN_C;
    int loc[SCAN_C];
    int s = 0;
#pragma unroll
    for (int i = 0; i < SCAN_C; i++) {
        int n = base + i;
        int c = (n < N_NODES) ? g_cnt[n] : 0;
        loc[i] = s; s += c;
    }
    part[t] = s;
    __syncthreads();
    for (int off = 1; off < SCAN_T; off <<= 1) {
        int v = (t >= off) ? part[t - off] : 0;
        __syncthreads();
        part[t] += v;
        __syncthreads();
    }
    int pre = (t > 0) ? part[t - 1] : 0;
#pragma unroll
    for (int i = 0; i < SCAN_C; i++) {
        int n = base + i;
        if (n < N_NODES) {
            int p = pre + loc[i];
            g_rowptr[n] = p;
            g_cur[n]    = p;
            g_dis[n]    = rsqrtf((float)g_cnt[n] + 1.0f);  // +1 self-loop
        }
    }
    if (t == SCAN_T - 1) g_rowptr[N_NODES] = part[t];
}
__global__ void k_fill(const void* __restrict__ ei) {
    int e = blockIdx.x * blockDim.x + threadIdx.x;
    if (e >= N_EDGES) return;
    int r = eidx(ei, e);
    int c = eidx(ei, N_EDGES + e);
    int p = atomicAdd(&g_cur[c], 1);
    g_src[p] = r;
    g_nrm[p] = g_dis[r] * g_dis[c];
}

// ---------------- aggregation: pure gather via CSR (no atomics) ----------------
__global__ void __launch_bounds__(128) k_gather512(const float* __restrict__ h,
                                                   float* __restrict__ agg) {
    int v = blockIdx.x;
    int t = threadIdx.x;
    int b = g_rowptr[v], e = g_rowptr[v + 1];
    float s = g_dis[v]; s *= s;
    float4 hv = *(const float4*)&h[(size_t)v * 512 + t * 4];
    float4 acc;
    acc.x = s * hv.x; acc.y = s * hv.y; acc.z = s * hv.z; acc.w = s * hv.w;
    for (int j = b; j < e; j++) {
        int   src = g_src[j];
        float nr  = g_nrm[j];
        float4 x = *(const float4*)&h[(size_t)src * 512 + t * 4];
        acc.x += nr * x.x; acc.y += nr * x.y;
        acc.z += nr * x.z; acc.w += nr * x.w;
    }
    *(float4*)&agg[(size_t)v * 512 + t * 4] = acc;
}
__global__ void __launch_bounds__(128) k_gather128(const float* __restrict__ h,
                                                   float* __restrict__ agg) {
    int v = blockIdx.x;
    int t = threadIdx.x;
    int b = g_rowptr[v], e = g_rowptr[v + 1];
    float s = g_dis[v]; s *= s;
    float acc = s * h[(size_t)v * 128 + t];
    for (int j = b; j < e; j++)
        acc += g_nrm[j] * h[(size_t)g_src[j] * 128 + t];
    agg[(size_t)v * 128 + t] = acc;
}

// ---------------- GCN GEMM + bias + ReLU + LayerNorm ----------------
__global__ void __launch_bounds__(256) k_gcn(
    const float* __restrict__ A, const float* __restrict__ W,
    const float* __restrict__ bias, const float* __restrict__ gam,
    const float* __restrict__ bet, float* __restrict__ out, int K)
{
    __shared__ float sA[16][16];
    __shared__ float sW[16][512];
    __shared__ float rsum[16][4], rsq[16][4];
    int t = threadIdx.x;
    int tx = t & 127, ty = t >> 7;
    int row0 = blockIdx.x * 16;
    unsigned long long a64[8][2];
#pragma unroll
    for (int j = 0; j < 8; j++) { a64[j][0] = 0ull; a64[j][1] = 0ull; }

    for (int k0 = 0; k0 < K; k0 += 16) {
        sA[t >> 4][t & 15] = A[(row0 + (t >> 4)) * K + k0 + (t & 15)];
#pragma unroll
        for (int i = 0; i < 8; i++) {
            int idx = t + i * 256;
            int kk = idx >> 7, c4 = idx & 127;
            *(float4*)&sW[kk][c4 * 4] = *(const float4*)&W[(k0 + kk) * 512 + c4 * 4];
        }
        __syncthreads();
#pragma unroll
        for (int kk = 0; kk < 16; kk++) {
            ulonglong2 w2 = *(ulonglong2*)&sW[kk][tx * 4];
#pragma unroll
            for (int j = 0; j < 8; j++) {
                unsigned long long aa = bcast2(sA[ty + j * 2][kk]);
                FMA2(a64[j][0], aa, w2.x);
                FMA2(a64[j][1], aa, w2.y);
            }
        }
        __syncthreads();
    }

    float acc[8][4];
#pragma unroll
    for (int j = 0; j < 8; j++) {
        unpack2(a64[j][0], acc[j][0], acc[j][1]);
        unpack2(a64[j][1], acc[j][2], acc[j][3]);
    }

    float4 b4 = *(const float4*)&bias[tx * 4];
    int lane = t & 31, quarter = (t >> 5) & 3;
#pragma unroll
    for (int j = 0; j < 8; j++) {
        acc[j][0] = fmaxf(acc[j][0] + b4.x, 0.f);
        acc[j][1] = fmaxf(acc[j][1] + b4.y, 0.f);
        acc[j][2] = fmaxf(acc[j][2] + b4.z, 0.f);
        acc[j][3] = fmaxf(acc[j][3] + b4.w, 0.f);
        int r = ty + j * 2;
        float s = acc[j][0] + acc[j][1] + acc[j][2] + acc[j][3];
        float q = acc[j][0]*acc[j][0] + acc[j][1]*acc[j][1]
                + acc[j][2]*acc[j][2] + acc[j][3]*acc[j][3];
        s = warp_sum(s); q = warp_sum(q);
        if (lane == 0) { rsum[r][quarter] = s; rsq[r][quarter] = q; }
    }
    __syncthreads();
    float4 g4  = *(const float4*)&gam[tx * 4];
    float4 be4 = *(const float4*)&bet[tx * 4];
#pragma unroll
    for (int j = 0; j < 8; j++) {
        int r = ty + j * 2;
        float s = rsum[r][0] + rsum[r][1] + rsum[r][2] + rsum[r][3];
        float q = rsq[r][0]  + rsq[r][1]  + rsq[r][2]  + rsq[r][3];
        float mu  = s * (1.f / 512.f);
        float var = q * (1.f / 512.f) - mu * mu;
        float rs  = rsqrtf(var + EPS);
        float4 o;
        o.x = (acc[j][0] - mu) * rs * g4.x + be4.x;
        o.y = (acc[j][1] - mu) * rs * g4.y + be4.y;
        o.z = (acc[j][2] - mu) * rs * g4.z + be4.z;
        o.w = (acc[j][3] - mu) * rs * g4.w + be4.w;
        *(float4*)&out[(row0 + r) * 512 + tx * 4] = o;
    }
}

// ---------------- tiled GEMM: C[N_PAD,1024] = Ain[N_PAD,512] @ W[512,1024] ----------------
__global__ void __launch_bounds__(256) k_gemm64(
    const float* __restrict__ Ain, const float* __restrict__ W, float* __restrict__ C)
{
    __shared__ float sA[64][20];
    __shared__ float sB[16][64];
    int t = threadIdx.x;
    int tx = t & 15, ty = t >> 4;
    int c0 = blockIdx.x * 64, r0 = blockIdx.y * 64;
    unsigned long long a64[4][2];
#pragma unroll
    for (int i = 0; i < 4; i++) { a64[i][0] = 0ull; a64[i][1] = 0ull; }

    for (int k0 = 0; k0 < 512; k0 += 16) {
        {
            int r = t >> 2, q = t & 3;
            *(float4*)&sA[r][q * 4] = *(const float4*)&Ain[(r0 + r) * 512 + k0 + q * 4];
        }
        {
            int kk = t >> 4, c4 = t & 15;
            *(float4*)&sB[kk][c4 * 4] = *(const float4*)&W[(size_t)(k0 + kk) * 1024 + c0 + c4 * 4];
        }
        __syncthreads();
#pragma unroll
        for (int kk = 0; kk < 16; kk++) {
            ulonglong2 b2 = *(ulonglong2*)&sB[kk][tx * 4];
#pragma unroll
            for (int i = 0; i < 4; i++) {
                unsigned long long aa = bcast2(sA[ty * 4 + i][kk]);
                FMA2(a64[i][0], aa, b2.x);
                FMA2(a64[i][1], aa, b2.y);
            }
        }
        __syncthreads();
    }
#pragma unroll
    for (int i = 0; i < 4; i++) {
        float4 o;
        unpack2(a64[i][0], o.x, o.y);
        unpack2(a64[i][1], o.z, o.w);
        *(float4*)&C[(size_t)(r0 + ty * 4 + i) * 1024 + c0 + tx * 4] = o;
    }
}

// ---------------- fused edge MLP (stages 1+2, tensor cores) ----------------
// Per 64-edge block:
//   pass 1: per-row LN stats of v = A[s]+B[t]+mb0   (streamed, no storage)
//   k-loop: stage relu(LN(v)) chunk as tf32 -> mma vs pre-converted W1
//   epilogue: bias, LN(512), relu, dot(mw2), +mb2
__global__ void __launch_bounds__(512, 1) k_edge12(
    const void* __restrict__ ei,
    const float* __restrict__ mb0, const float* __restrict__ mg0,
    const float* __restrict__ mbt0,
    const float* __restrict__ mb1,
    const float* __restrict__ g, const float* __restrict__ bt,
    const float* __restrict__ mw2, const float* __restrict__ mb2,
    float* __restrict__ out)
{
    __shared__ unsigned sWu[16][520];
    __shared__ unsigned sZu[64][20];
    __shared__ float ps[64][4], pq[64][4], pd[64][4];
    __shared__ int   sS[64], sD[64];
    __shared__ float sMu[64], sRs[64];

    int t = threadIdx.x;
    int w = t >> 5, lane = t & 31;
    int gq = lane >> 2, tig = lane & 3;
    int row_half = w & 3, s = w >> 2;
    int lr0 = row_half * 16;
    int c0s = s * 128;
    int e0 = blockIdx.x * 64;

    if (t < 64) {
        sS[t] = eidx(ei, e0 + t);
        sD[t] = eidx(ei, N_EDGES + e0 + t);
    }
    __syncthreads();

    // ---- pass 1: LN stats (each warp: 4 rows) ----
#pragma unroll
    for (int rr = 0; rr < 4; rr++) {
        int r = w * 4 + rr;
        const float* pa = &g_A[(size_t)sS[r] * 1024];
        const float* pb = &g_B[(size_t)sD[r] * 1024];
        float sm = 0.f, sq = 0.f;
#pragma unroll
        for (int i = 0; i < 8; i++) {
            int c = i * 128 + lane * 4;
            float4 a = *(const float4*)&pa[c];
            float4 b = *(const float4*)&pb[c];
            float4 m = *(const float4*)&mb0[c];
            float v0 = a.x + b.x + m.x, v1 = a.y + b.y + m.y;
            float v2 = a.z + b.z + m.z, v3 = a.w + b.w + m.w;
            sm += v0 + v1 + v2 + v3;
            sq += v0*v0 + v1*v1 + v2*v2 + v3*v3;
        }
        sm = warp_sum(sm); sq = warp_sum(sq);
        if (lane == 0) {
            float mu = sm * (1.f / 1024.f);
            float var = sq * (1.f / 1024.f) - mu * mu;
            sMu[r] = mu;
            sRs[r] = rsqrtf(var + EPS);
        }
    }
    __syncthreads();

    float acc[16][4];
#pragma unroll
    for (int i = 0; i < 16; i++) { acc[i][0]=0.f; acc[i][1]=0.f; acc[i][2]=0.f; acc[i][3]=0.f; }

    int zrow = t >> 3, zkk = (t & 7) * 2;
    const float* zpa = &g_A[(size_t)sS[zrow] * 1024];
    const float* zpb = &g_B[(size_t)sD[zrow] * 1024];
    float zmu = sMu[zrow], zrs = sRs[zrow];

    for (int k0 = 0; k0 < 1024; k0 += 16) {
        // stage Z chunk: recompute relu(LN(A[s]+B[t]+mb0)) inline
        {
            int c = k0 + zkk;
            float2 a2 = *(const float2*)&zpa[c];
            float2 b2 = *(const float2*)&zpb[c];
            float2 m2 = *(const float2*)&mb0[c];
            float2 gg = *(const float2*)&mg0[c];
            float2 bb = *(const float2*)&mbt0[c];
            float z0 = fmaxf((a2.x + b2.x + m2.x - zmu) * zrs * gg.x + bb.x, 0.f);
            float z1 = fmaxf((a2.y + b2.y + m2.y - zmu) * zrs * gg.y + bb.y, 0.f);
            sZu[zrow][zkk]     = tf32cvt(z0);
            sZu[zrow][zkk + 1] = tf32cvt(z1);
        }
        // stage W chunk (pre-converted tf32)
#pragma unroll
        for (int i = 0; i < 4; i++) {
            int vi = t + i * 512;
            int kk = vi >> 7, c4 = vi & 127;
            *(uint4*)&sWu[kk][c4 * 4] = *(const uint4*)&g_W1t[(size_t)(k0 + kk) * 512 + c4 * 4];
        }
        __syncthreads();
#pragma unroll
        for (int k8 = 0; k8 < 16; k8 += 8) {
            unsigned a0 = sZu[lr0 + gq    ][k8 + tig];
            unsigned a1 = sZu[lr0 + gq + 8][k8 + tig];
            unsigned a2 = sZu[lr0 + gq    ][k8 + tig + 4];
            unsigned a3 = sZu[lr0 + gq + 8][k8 + tig + 4];
#pragma unroll
            for (int i = 0; i < 16; i++) {
                unsigned b0 = sWu[k8 + tig    ][c0s + i * 8 + gq];
                unsigned b1 = sWu[k8 + tig + 4][c0s + i * 8 + gq];
                mma_tf32(acc[i], a0, a1, a2, a3, b0, b1);
            }
        }
        __syncthreads();
    }

    int rA = lr0 + gq, rB = rA + 8;

    float sA = 0.f, qA = 0.f, sB = 0.f, qB = 0.f;
#pragma unroll
    for (int i = 0; i < 16; i++) {
        int col = c0s + i * 8 + 2 * tig;
        float2 b2 = *(const float2*)&mb1[col];
        acc[i][0] += b2.x; acc[i][1] += b2.y;
        acc[i][2] += b2.x; acc[i][3] += b2.y;
        sA += acc[i][0] + acc[i][1];
        qA += acc[i][0]*acc[i][0] + acc[i][1]*acc[i][1];
        sB += acc[i][2] + acc[i][3];
        qB += acc[i][2]*acc[i][2] + acc[i][3]*acc[i][3];
    }
#pragma unroll
    for (int o = 1; o <= 2; o <<= 1) {
        sA += __shfl_xor_sync(0xffffffffu, sA, o);
        qA += __shfl_xor_sync(0xffffffffu, qA, o);
        sB += __shfl_xor_sync(0xffffffffu, sB, o);
        qB += __shfl_xor_sync(0xffffffffu, qB, o);
    }
    if (tig == 0) { ps[rA][s] = sA; pq[rA][s] = qA; ps[rB][s] = sB; pq[rB][s] = qB; }
    __syncthreads();

    float SA = ps[rA][0] + ps[rA][1] + ps[rA][2] + ps[rA][3];
    float QA = pq[rA][0] + pq[rA][1] + pq[rA][2] + pq[rA][3];
    float SB = ps[rB][0] + ps[rB][1] + ps[rB][2] + ps[rB][3];
    float QB = pq[rB][0] + pq[rB][1] + pq[rB][2] + pq[rB][3];
    float muA = SA * (1.f / 512.f);
    float rsA = rsqrtf(QA * (1.f / 512.f) - muA * muA + EPS);
    float muB = SB * (1.f / 512.f);
    float rsB = rsqrtf(QB * (1.f / 512.f) - muB * muB + EPS);

    float dA = 0.f, dB = 0.f;
#pragma unroll
    for (int i = 0; i < 16; i++) {
        int col = c0s + i * 8 + 2 * tig;
        float2 gm = *(const float2*)&g[col];
        float2 bb = *(const float2*)&bt[col];
        float2 w2 = *(const float2*)&mw2[col];
        dA += fmaxf((acc[i][0] - muA) * rsA * gm.x + bb.x, 0.f) * w2.x
            + fmaxf((acc[i][1] - muA) * rsA * gm.y + bb.y, 0.f) * w2.y;
        dB += fmaxf((acc[i][2] - muB) * rsB * gm.x + bb.x, 0.f) * w2.x
            + fmaxf((acc[i][3] - muB) * rsB * gm.y + bb.y, 0.f) * w2.y;
    }
#pragma unroll
    for (int o = 1; o <= 2; o <<= 1) {
        dA += __shfl_xor_sync(0xffffffffu, dA, o);
        dB += __shfl_xor_sync(0xffffffffu, dB, o);
    }
    if (tig == 0) { pd[rA][s] = dA; pd[rB][s] = dB; }
    __syncthreads();

    if (t < 64)
        out[e0 + t] = pd[t][0] + pd[t][1] + pd[t][2] + pd[t][3] + mb2[0];
}

// ---------------- launch ----------------
extern "C" void kernel_launch(void* const* d_in, const int* in_sizes, int n_in,
                              void* d_out, int out_size)
{
    const float* x    = (const float*)d_in[0];
    const void*  ei   = d_in[1];
    const float* w0   = (const float*)d_in[2];
    const float* b0   = (const float*)d_in[3];
    const float* ws   = (const float*)d_in[4];
    const float* bs   = (const float*)d_in[5];
    const float* lng  = (const float*)d_in[6];
    const float* lnb  = (const float*)d_in[7];
    const float* mw0  = (const float*)d_in[8];
    const float* mb0  = (const float*)d_in[9];
    const float* mg0  = (const float*)d_in[10];
    const float* mbt0 = (const float*)d_in[11];
    const float* mw1  = (const float*)d_in[12];
    const float* mb1  = (const float*)d_in[13];
    const float* mg1  = (const float*)d_in[14];
    const float* mbt1 = (const float*)d_in[15];
    const float* mw2  = (const float*)d_in[16];
    const float* mb2  = (const float*)d_in[17];
    float* out = (float*)d_out;

    float *p_agg, *p_h, *p_A, *p_B;
    cudaGetSymbolAddress((void**)&p_agg, g_agg);
    cudaGetSymbolAddress((void**)&p_h,   g_h);
    cudaGetSymbolAddress((void**)&p_A,   g_A);
    cudaGetSymbolAddress((void**)&p_B,   g_B);

    // dtype detect + CSR build + W1 tf32 pre-convert
    k_detect<<<1, 32>>>((const int*)ei);
    k_cnt_zero<<<(N_NODES + 255) / 256, 256>>>();
    k_cnt_acc <<<(N_EDGES + 255) / 256, 256>>>(ei);
    k_scan<<<1, SCAN_T>>>();
    k_fill<<<(N_EDGES + 255) / 256, 256>>>(ei);
    k_w1cvt<<<512, 256>>>(mw1);

    // layer 0 (aggregate in 128-dim input space, then GEMM 128->512)
    k_gather128<<<N_NODES, 128>>>(x, p_agg);
    k_gcn<<<N_NODES / 16, 256>>>(p_agg, w0, b0, lng, lnb, p_h, 128);

    // layers 1..3
    for (int i = 1; i < 4; i++) {
        k_gather512<<<N_NODES, 128>>>(p_h, p_agg);
        k_gcn<<<N_NODES / 16, 256>>>(p_agg, ws + (size_t)(i - 1) * 512 * 512,
                                     bs + (i - 1) * 512, lng + i * 512, lnb + i * 512,
                                     p_h, 512);
    }

    // edge MLP first layer factored per-node: A = h @ mw0[:512], B = h @ mw0[512:]
    dim3 gAB(16, N_PAD / 64);
    k_gemm64<<<gAB, 256>>>(p_h, mw0, p_A);
    k_gemm64<<<gAB, 256>>>(p_h, mw0 + (size_t)512 * 1024, p_B);

    // fused: relu(LN(A[s]+B[t]+mb0)) @ mw1 -> LN -> relu -> dot(mw2) + mb2
    k_edge12<<<N_EDGES / 64, 512>>>(ei, mb0, mg0, mbt0,
                                    mb1, mg1, mbt1, mw2, mb2, out);
}